// round 6
// baseline (speedup 1.0000x reference)
#include <cuda_runtime.h>
#include <cstdint>

#define T_ 512
#define B_ 4
#define H_ 16
#define D_ 64
#define NBKT 32
#define TOKENS 1536           // (1+NGRAM)*T
#define ROWS_ (TOKENS * B_)   // 6144
#define GK 1024               // K for all GEMMs
#define BK 32                 // K chunk
#define NCHUNK (GK / BK)      // 32

typedef unsigned long long ull;

// Scratch (device globals: allocation-free rule)
__device__ float g_qkv[ROWS_ * 3072];  // q|k|v per row, q pre-scaled by 1/8
__device__ float g_rel[ROWS_ * 512];   // rel-value table, col = bucket*16 + head
__device__ float g_ctx[ROWS_ * 1024];  // attention output pre out-proj

// ---- packed f32x2 helpers (attention kernel) ----
__device__ __forceinline__ ull dup2(float x) {
    ull r; asm("mov.b64 %0, {%1, %2};" : "=l"(r) : "f"(x), "f"(x)); return r;
}
__device__ __forceinline__ float2 unpack2(ull v) {
    float2 f; asm("mov.b64 {%0, %1}, %2;" : "=f"(f.x), "=f"(f.y) : "l"(v)); return f;
}
__device__ __forceinline__ void fma2(ull& d, ull a, ull b) {
    asm("fma.rn.f32x2 %0, %1, %2, %0;" : "+l"(d) : "l"(a), "l"(b));
}
__device__ __forceinline__ ull mul2(ull a, ull b) {
    ull r; asm("mul.rn.f32x2 %0, %1, %2;" : "=l"(r) : "l"(a), "l"(b)); return r;
}

// ---- tf32 helpers (arch-generic: sm_80+) ----
__device__ __forceinline__ float f2tf(float f) {
    uint32_t r; asm("cvt.rna.tf32.f32 %0, %1;" : "=r"(r) : "f"(f));
    return __uint_as_float(r);
}
__device__ __forceinline__ void mma_tf32(float* c, const float4& a, const float2& b) {
    asm volatile(
        "mma.sync.aligned.m16n8k8.row.col.f32.tf32.tf32.f32 "
        "{%0,%1,%2,%3}, {%4,%5,%6,%7}, {%8,%9}, {%0,%1,%2,%3};"
        : "+f"(c[0]), "+f"(c[1]), "+f"(c[2]), "+f"(c[3])
        : "r"(__float_as_uint(a.x)), "r"(__float_as_uint(a.y)),
          "r"(__float_as_uint(a.z)), "r"(__float_as_uint(a.w)),
          "r"(__float_as_uint(b.x)), "r"(__float_as_uint(b.y)));
}

// ---------------------------------------------------------------------------
// tf32 mma.sync GEMM: C[M,N] = A[M,K=1024] @ B[N,K]^T + bias,
// cols < scale_cols scaled by `scale`.
// 128x128 CTA tile, 8 warps (each 64x32), BK=32 double-buffered smem in
// FRAGMENT ORDER: A slot (mt,ks): 32 lanes x float4; B slot (nt,ks): 32 x float2.
// ---------------------------------------------------------------------------
#define ASLOT_F 128          // floats per A slot (32 lanes * 4)
#define BSLOT_F 64           // floats per B slot (32 lanes * 2)
#define ABUF_F  (32 * ASLOT_F)   // 8 mt * 4 ks = 32 slots = 4096 floats
#define BBUF_F  (64 * BSLOT_F)   // 16 nt * 4 ks = 64 slots = 4096 floats
#define SMEM_GEMM ((2 * ABUF_F + 2 * BBUF_F) * 4)   // 64 KB

__global__ __launch_bounds__(256, 1) void gemm_mma(
    const float* __restrict__ A, const float* __restrict__ Bm,
    const float* __restrict__ bias, float* __restrict__ C,
    int M, int N, int scale_cols, float scale)
{
    extern __shared__ float smem[];
    float* As = smem;                       // [2][ABUF_F]
    float* Bs = smem + 2 * ABUF_F;          // [2][BBUF_F]

    const int tid  = threadIdx.x;
    const int wid  = tid >> 5;
    const int lane = tid & 31;
    const int row0 = blockIdx.y * 128;
    const int col0 = blockIdx.x * 128;
    const int wm   = wid >> 2;              // 0..1  (m offset wm*64)
    const int wn   = wid & 3;               // 0..3  (n offset wn*32)

    const int lq = lane >> 2;               // 0..7
    const int lr = lane & 3;                // 0..3

    float acc[4][4][4];
    #pragma unroll
    for (int i = 0; i < 4; i++)
        #pragma unroll
        for (int j = 0; j < 4; j++)
            #pragma unroll
            for (int q = 0; q < 4; q++) acc[i][j][q] = 0.f;

    float4 va[4];
    float2 vb[8];

    // gmem fetch of chunk k0 into regs (fragment-gather)
    auto fetch = [&](int k0) {
        #pragma unroll
        for (int i = 0; i < 4; i++) {
            int combo = wid * 4 + i;        // mt = combo>>2, ks = combo&3
            int mt = combo >> 2, ks = combo & 3;
            const float* p = A + (size_t)(row0 + mt*16 + lq) * GK + (k0 + ks*8 + lr);
            va[i].x = p[0];
            va[i].y = p[(size_t)8 * GK];
            va[i].z = p[4];
            va[i].w = p[(size_t)8 * GK + 4];
        }
        #pragma unroll
        for (int i = 0; i < 8; i++) {
            int combo = wid * 8 + i;        // nt = combo>>2, ks = combo&3
            int nt = combo >> 2, ks = combo & 3;
            const float* p = Bm + (size_t)(col0 + nt*8 + lq) * GK + (k0 + ks*8 + lr);
            vb[i].x = p[0];
            vb[i].y = p[4];
        }
    };
    auto stage = [&](int buf) {
        float* ab = As + buf * ABUF_F;
        float* bb = Bs + buf * BBUF_F;
        #pragma unroll
        for (int i = 0; i < 4; i++) {
            int combo = wid * 4 + i;
            *(float4*)&ab[combo * ASLOT_F + lane * 4] =
                make_float4(f2tf(va[i].x), f2tf(va[i].y), f2tf(va[i].z), f2tf(va[i].w));
        }
        #pragma unroll
        for (int i = 0; i < 8; i++) {
            int combo = wid * 8 + i;
            *(float2*)&bb[combo * BSLOT_F + lane * 2] =
                make_float2(f2tf(vb[i].x), f2tf(vb[i].y));
        }
    };

    fetch(0);
    stage(0);
    __syncthreads();

    for (int it = 0; it < NCHUNK; it++) {
        const int cur = it & 1;
        if (it + 1 < NCHUNK) fetch((it + 1) * BK);

        const float* ab = As + cur * ABUF_F;
        const float* bb = Bs + cur * BBUF_F;
        #pragma unroll
        for (int ks = 0; ks < 4; ks++) {
            float4 af[4]; float2 bf[4];
            #pragma unroll
            for (int mt = 0; mt < 4; mt++)
                af[mt] = *(const float4*)&ab[((wm*4 + mt)*4 + ks) * ASLOT_F + lane*4];
            #pragma unroll
            for (int nt = 0; nt < 4; nt++)
                bf[nt] = *(const float2*)&bb[((wn*4 + nt)*4 + ks) * BSLOT_F + lane*2];
            #pragma unroll
            for (int mt = 0; mt < 4; mt++)
                #pragma unroll
                for (int nt = 0; nt < 4; nt++)
                    mma_tf32(acc[mt][nt], af[mt], bf[nt]);
        }

        if (it + 1 < NCHUNK) {
            stage(cur ^ 1);
            __syncthreads();
        }
    }

    // epilogue: c0,c1 -> (row, col..col+1); c2,c3 -> (row+8, col..col+1)
    #pragma unroll
    for (int mt = 0; mt < 4; mt++) {
        int rg0 = row0 + wm*64 + mt*16 + lq;
        #pragma unroll
        for (int nt = 0; nt < 4; nt++) {
            int cg = col0 + wn*32 + nt*8 + lr*2;
            float2 bv = *(const float2*)&bias[cg];
            float s = (cg < scale_cols) ? scale : 1.f;
            float2 o0 = make_float2((acc[mt][nt][0] + bv.x) * s,
                                    (acc[mt][nt][1] + bv.y) * s);
            float2 o1 = make_float2((acc[mt][nt][2] + bv.x) * s,
                                    (acc[mt][nt][3] + bv.y) * s);
            *(float2*)&C[(size_t)rg0 * N + cg]       = o0;
            *(float2*)&C[(size_t)(rg0 + 8) * N + cg] = o1;
        }
    }
}

// ---------------------------------------------------------------------------
// Fused flash attention (main + ngram in one launch), BM=64 x BN=64, d=64.
// grid: (T/64, B*H, 3) — z=0: main (S=512), z=1,2: ngram n=z-1 (S=1024).
// ---------------------------------------------------------------------------
#define BM2 64
#define BN2 64
#define DP  68

__global__ __launch_bounds__(256) void attn_kernel(
    const float* __restrict__ qkv, const float* __restrict__ rel,
    const float* __restrict__ mask_main, const float* __restrict__ mask_ng,
    const int* __restrict__ ib_main, const int* __restrict__ ib_ng,
    float* __restrict__ ctx)
{
    extern __shared__ float sm[];
    float* sQt   = sm;                 // [64][DP]  Q^T (k-major)
    float* sK    = sQt + 64*DP;        // [64][DP]  K^T, later V[s][d]
    float* sP    = sK  + 64*DP;        // [64][DP]
    float* sRel  = sP  + 64*DP;        // [64][32]
    float* sM    = sRel + 64*32;
    float* sL    = sM + 64;
    float* sScale= sL + 64;

    const int bh = blockIdx.y;
    const int b  = bh >> 4;
    const int h  = bh & 15;
    const int z  = blockIdx.z;
    const int is_ng = (z > 0);
    const int n  = z - 1;
    const int t0 = blockIdx.x * BM2;
    const int S  = is_ng ? 1024 : 512;
    const int qtok0 = is_ng ? (T_ + n*T_ + t0) : t0;
    const float* maskrow = is_ng ? (mask_ng + (size_t)n * T_ * 1024) : mask_main;
    const int*   brow    = is_ng ? (ib_ng + (size_t)b * T_ * 1024)
                                 : (ib_main + (size_t)b * T_ * 512);

    const int tid = threadIdx.x;
    const int tx  = tid & 15, ty = tid >> 4;

    #pragma unroll
    for (int p = 0; p < 4; p++) {
        int idx = tid + p*256;
        int r  = idx >> 4;
        int c4 = (idx & 15) << 2;
        float4 v = *(const float4*)(qkv + (size_t)((qtok0 + r)*B_ + b)*3072 + h*D_ + c4);
        sQt[(c4+0)*DP + r] = v.x; sQt[(c4+1)*DP + r] = v.y;
        sQt[(c4+2)*DP + r] = v.z; sQt[(c4+3)*DP + r] = v.w;
    }
    #pragma unroll
    for (int p = 0; p < 8; p++) {
        int idx = tid + p*256;
        int r = idx >> 5, bk = idx & 31;
        sRel[r*32 + bk] = rel[(size_t)((qtok0 + r)*B_ + b)*512 + bk*H_ + h];
    }
    if (tid < 64) { sM[tid] = -1e30f; sL[tid] = 0.f; }

    ull accO[4][2];
    #pragma unroll
    for (int i = 0; i < 4; i++) { accO[i][0] = 0ull; accO[i][1] = 0ull; }

    for (int s0 = 0; s0 < S; s0 += BN2) {
        __syncthreads();
        #pragma unroll
        for (int p = 0; p < 4; p++) {
            int idx = tid + p*256;
            int sr = idx >> 4;
            int c4 = (idx & 15) << 2;
            int sg = s0 + sr;
            int tok = (!is_ng || sg < T_) ? sg : (T_ + n*T_ + (sg - T_));
            float4 v = *(const float4*)(qkv + (size_t)(tok*B_ + b)*3072 + 1024 + h*D_ + c4);
            sK[(c4+0)*DP + sr] = v.x; sK[(c4+1)*DP + sr] = v.y;
            sK[(c4+2)*DP + sr] = v.z; sK[(c4+3)*DP + sr] = v.w;
        }
        __syncthreads();

        ull acc[4][2];
        #pragma unroll
        for (int i = 0; i < 4; i++) { acc[i][0] = 0ull; acc[i][1] = 0ull; }
        #pragma unroll 8
        for (int kk = 0; kk < D_; kk++) {
            float4 a = *(const float4*)&sQt[kk*DP + ty*4];
            ull b0 = *(const ull*)&sK[kk*DP + tx*4];
            ull b1 = *(const ull*)&sK[kk*DP + tx*4 + 2];
            ull d;
            d = dup2(a.x); fma2(acc[0][0], d, b0); fma2(acc[0][1], d, b1);
            d = dup2(a.y); fma2(acc[1][0], d, b0); fma2(acc[1][1], d, b1);
            d = dup2(a.z); fma2(acc[2][0], d, b0); fma2(acc[2][1], d, b1);
            d = dup2(a.w); fma2(acc[3][0], d, b0); fma2(acc[3][1], d, b1);
        }
        #pragma unroll
        for (int i = 0; i < 4; i++) {
            int r  = ty*4 + i;
            int tg = t0 + r;
            const size_t base = (size_t)tg * S + s0 + tx*4;
            int4   bk = *(const int4*)&brow[base];
            float4 mk = *(const float4*)&maskrow[base];
            float2 v0 = unpack2(acc[i][0]);
            float2 v1 = unpack2(acc[i][1]);
            float4 o;
            o.x = v0.x + sRel[r*32 + bk.x] + mk.x;
            o.y = v0.y + sRel[r*32 + bk.y] + mk.y;
            o.z = v1.x + sRel[r*32 + bk.z] + mk.z;
            o.w = v1.y + sRel[r*32 + bk.w] + mk.w;
            *(float4*)&sP[r*DP + tx*4] = o;
        }
        __syncthreads();

        #pragma unroll
        for (int p = 0; p < 4; p++) {
            int idx = tid + p*256;
            int sr = idx >> 4;
            int c4 = (idx & 15) << 2;
            int sg = s0 + sr;
            int tok = (!is_ng || sg < T_) ? sg : (T_ + n*T_ + (sg - T_));
            float4 v = *(const float4*)(qkv + (size_t)(tok*B_ + b)*3072 + 2048 + h*D_ + c4);
            *(float4*)&sK[sr*DP + c4] = v;
        }

        {
            int r = tid >> 2, g = tid & 3;
            float* row = &sP[r*DP + g*16];
            float4 x0 = *(const float4*)(row);
            float4 x1 = *(const float4*)(row + 4);
            float4 x2 = *(const float4*)(row + 8);
            float4 x3 = *(const float4*)(row + 12);
            float mx = fmaxf(fmaxf(fmaxf(x0.x,x0.y),fmaxf(x0.z,x0.w)),
                      fmaxf(fmaxf(fmaxf(x1.x,x1.y),fmaxf(x1.z,x1.w)),
                      fmaxf(fmaxf(fmaxf(x2.x,x2.y),fmaxf(x2.z,x2.w)),
                            fmaxf(fmaxf(x3.x,x3.y),fmaxf(x3.z,x3.w)))));
            mx = fmaxf(mx, __shfl_xor_sync(0xffffffffu, mx, 1));
            mx = fmaxf(mx, __shfl_xor_sync(0xffffffffu, mx, 2));
            float oldm = sM[r];
            float newm = fmaxf(oldm, mx);
            x0.x = __expf(x0.x - newm); x0.y = __expf(x0.y - newm);
            x0.z = __expf(x0.z - newm); x0.w = __expf(x0.w - newm);
            x1.x = __expf(x1.x - newm); x1.y = __expf(x1.y - newm);
            x1.z = __expf(x1.z - newm); x1.w = __expf(x1.w - newm);
            x2.x = __expf(x2.x - newm); x2.y = __expf(x2.y - newm);
            x2.z = __expf(x2.z - newm); x2.w = __expf(x2.w - newm);
            x3.x = __expf(x3.x - newm); x3.y = __expf(x3.y - newm);
            x3.z = __expf(x3.z - newm); x3.w = __expf(x3.w - newm);
            float sum = (x0.x+x0.y+x0.z+x0.w) + (x1.x+x1.y+x1.z+x1.w)
                      + (x2.x+x2.y+x2.z+x2.w) + (x3.x+x3.y+x3.z+x3.w);
            sum += __shfl_xor_sync(0xffffffffu, sum, 1);
            sum += __shfl_xor_sync(0xffffffffu, sum, 2);
            *(float4*)(row)      = x0;
            *(float4*)(row + 4)  = x1;
            *(float4*)(row + 8)  = x2;
            *(float4*)(row + 12) = x3;
            if (g == 0) {
                float scl = __expf(oldm - newm);
                sScale[r] = scl;
                sL[r] = sL[r]*scl + sum;
                sM[r] = newm;
            }
        }
        __syncthreads();

        #pragma unroll
        for (int i = 0; i < 4; i++) {
            ull f = dup2(sScale[ty*4 + i]);
            accO[i][0] = mul2(accO[i][0], f);
            accO[i][1] = mul2(accO[i][1], f);
        }
        #pragma unroll 8
        for (int s = 0; s < BN2; s++) {
            ull v0 = *(const ull*)&sK[s*DP + tx*4];
            ull v1 = *(const ull*)&sK[s*DP + tx*4 + 2];
            ull p;
            p = dup2(sP[(ty*4+0)*DP + s]); fma2(accO[0][0], p, v0); fma2(accO[0][1], p, v1);
            p = dup2(sP[(ty*4+1)*DP + s]); fma2(accO[1][0], p, v0); fma2(accO[1][1], p, v1);
            p = dup2(sP[(ty*4+2)*DP + s]); fma2(accO[2][0], p, v0); fma2(accO[2][1], p, v1);
            p = dup2(sP[(ty*4+3)*DP + s]); fma2(accO[3][0], p, v0); fma2(accO[3][1], p, v1);
        }
    }

    #pragma unroll
    for (int i = 0; i < 4; i++) {
        int r = ty*4 + i;
        float inv = 1.f / sL[r];
        float2 a = unpack2(accO[i][0]);
        float2 c = unpack2(accO[i][1]);
        float4 o = make_float4(a.x*inv, a.y*inv, c.x*inv, c.y*inv);
        *(float4*)(ctx + (size_t)((qtok0 + r)*B_ + b)*1024 + h*D_ + tx*4) = o;
    }
}

#define SMEM_ATTN ((3*64*DP + 64*32 + 3*64) * 4)

// ---------------------------------------------------------------------------
extern "C" void kernel_launch(void* const* d_in, const int* in_sizes, int n_in,
                              void* d_out, int out_size)
{
    const float* hs        = (const float*)d_in[0];   // (1536,4,1024)
    const float* w_in      = (const float*)d_in[1];   // (3072,1024)
    const float* b_in      = (const float*)d_in[2];   // (3072,)
    const float* rw        = (const float*)d_in[3];   // (512,1024)
    const float* rb        = (const float*)d_in[4];   // (512,)
    const float* ow        = (const float*)d_in[5];   // (1024,1024)
    const float* ob        = (const float*)d_in[6];   // (1024,)
    const float* mask_main = (const float*)d_in[7];   // (512,512)
    const float* mask_ng   = (const float*)d_in[8];   // (2,512,1024)
    const int*   ib_main   = (const int*)d_in[9];     // (4,512,512)
    const int*   ib_ng     = (const int*)d_in[10];    // (4,512,1024)
    float* out = (float*)d_out;

    float *qkv, *rel, *ctx;
    cudaGetSymbolAddress((void**)&qkv, g_qkv);
    cudaGetSymbolAddress((void**)&rel, g_rel);
    cudaGetSymbolAddress((void**)&ctx, g_ctx);

    cudaFuncSetAttribute(gemm_mma, cudaFuncAttributeMaxDynamicSharedMemorySize, SMEM_GEMM);
    cudaFuncSetAttribute(attn_kernel, cudaFuncAttributeMaxDynamicSharedMemorySize, SMEM_ATTN);

    // QKV projection (tf32 mma.sync); q cols [0,1024) pre-scaled by 0.125
    gemm_mma<<<dim3(3072/128, ROWS_/128), 256, SMEM_GEMM>>>(
        hs, w_in, b_in, qkv, ROWS_, 3072, 1024, 0.125f);
    // rel-value table
    gemm_mma<<<dim3(512/128, ROWS_/128), 256, SMEM_GEMM>>>(
        hs, rw, rb, rel, ROWS_, 512, 0, 1.f);
    // fused attention: z=0 main, z=1,2 ngram
    attn_kernel<<<dim3(T_/BM2, B_*H_, 3), 256, SMEM_ATTN>>>(
        qkv, rel, mask_main, mask_ng, ib_main, ib_ng, ctx);
    // out projection directly into d_out
    gemm_mma<<<dim3(1024/128, ROWS_/128), 256, SMEM_GEMM>>>(
        ctx, ow, ob, out, ROWS_, 1024, 0, 1.f);
}

// round 8
// speedup vs baseline: 2.0280x; 2.0280x over previous
#include <cuda_runtime.h>
#include <cstdint>

#define T_ 512
#define B_ 4
#define H_ 16
#define D_ 64
#define NBKT 32
#define TOKENS 1536           // (1+NGRAM)*T
#define ROWS_ (TOKENS * B_)   // 6144
#define GK 1024               // K for all GEMMs
#define BK 32                 // K chunk
#define NCHUNK (GK / BK)      // 32
#define LDS_ 36               // smem row stride (floats): conflict-free frags
#define TILE_F (128 * LDS_)   // 4608 floats per tile
#define STAGE_F (2 * TILE_F)  // A tile + B tile per stage
#define NSTAGE 3
#define SMEM_GEMM (NSTAGE * STAGE_F * 4)   // 110592 B

typedef unsigned long long ull;

// Scratch (device globals: allocation-free rule)
__device__ float g_qkv[ROWS_ * 3072];  // q|k|v per row, q pre-scaled by 1/8
__device__ float g_rel[ROWS_ * 512];   // rel-value table, col = bucket*16 + head
__device__ float g_ctx[ROWS_ * 1024];  // attention output pre out-proj

// ---- packed f32x2 helpers (attention kernel) ----
__device__ __forceinline__ ull dup2(float x) {
    ull r; asm("mov.b64 %0, {%1, %2};" : "=l"(r) : "f"(x), "f"(x)); return r;
}
__device__ __forceinline__ float2 unpack2(ull v) {
    float2 f; asm("mov.b64 {%0, %1}, %2;" : "=f"(f.x), "=f"(f.y) : "l"(v)); return f;
}
__device__ __forceinline__ void fma2(ull& d, ull a, ull b) {
    asm("fma.rn.f32x2 %0, %1, %2, %0;" : "+l"(d) : "l"(a), "l"(b));
}
__device__ __forceinline__ ull mul2(ull a, ull b) {
    ull r; asm("mul.rn.f32x2 %0, %1, %2;" : "=l"(r) : "l"(a), "l"(b)); return r;
}

// ---- tf32 helpers (arch-generic: sm_80+) ----
__device__ __forceinline__ uint32_t f2tfu(float f) {
    uint32_t r; asm("cvt.rna.tf32.f32 %0, %1;" : "=r"(r) : "f"(f));
    return r;
}
__device__ __forceinline__ void mma_tf32(float* c, const uint32_t* a, const uint32_t* b) {
    asm volatile(
        "mma.sync.aligned.m16n8k8.row.col.f32.tf32.tf32.f32 "
        "{%0,%1,%2,%3}, {%4,%5,%6,%7}, {%8,%9}, {%0,%1,%2,%3};"
        : "+f"(c[0]), "+f"(c[1]), "+f"(c[2]), "+f"(c[3])
        : "r"(a[0]), "r"(a[1]), "r"(a[2]), "r"(a[3]), "r"(b[0]), "r"(b[1]));
}
__device__ __forceinline__ uint32_t smem_u32(const void* p) {
    uint32_t a;
    asm("{ .reg .u64 t; cvta.to.shared.u64 t, %1; cvt.u32.u64 %0, t; }" : "=r"(a) : "l"(p));
    return a;
}
__device__ __forceinline__ void cp16(uint32_t dst, const void* src) {
    asm volatile("cp.async.ca.shared.global [%0], [%1], 16;" :: "r"(dst), "l"(src));
}

// ---------------------------------------------------------------------------
// tf32 mma.sync GEMM: C[M,N] = A[M,K=1024] @ B[N,K]^T + bias,
// cols < scale_cols scaled by `scale`.
// 128x128 CTA tile, 8 warps (warp tile 64x32), cp.async 3-stage pipeline,
// row-major smem (stride 36 -> conflict-free LDS.32 fragments), cvt at use.
// ---------------------------------------------------------------------------
__global__ __launch_bounds__(256, 2) void gemm_mma(
    const float* __restrict__ A, const float* __restrict__ Bm,
    const float* __restrict__ bias, float* __restrict__ C,
    int M, int N, int scale_cols, float scale)
{
    extern __shared__ float smem[];
    const uint32_t sb = smem_u32(smem);

    const int tid  = threadIdx.x;
    const int wid  = tid >> 5;
    const int lane = tid & 31;
    const int row0 = blockIdx.y * 128;
    const int col0 = blockIdx.x * 128;
    const int wm   = wid >> 2;              // 0..1  (m offset wm*64)
    const int wn   = wid & 3;               // 0..3  (n offset wn*32)
    const int lq   = lane >> 2;             // 0..7
    const int lr   = lane & 3;              // 0..3

    // staging map: seg id s = tid + j*256 (j<4): row = s>>3, seg8 = s&7
    const int srow = tid >> 3;              // base row (tid part)
    const int sseg = tid & 7;

    float acc[4][4][4];
    #pragma unroll
    for (int i = 0; i < 4; i++)
        #pragma unroll
        for (int j = 0; j < 4; j++)
            #pragma unroll
            for (int q = 0; q < 4; q++) acc[i][j][q] = 0.f;

    const float* Abase = A  + (size_t)row0 * GK;
    const float* Bbase = Bm + (size_t)col0 * GK;

    auto issue_chunk = [&](int chunk, int stg) {
        const int k0 = chunk * BK;
        const uint32_t as = sb + (uint32_t)(stg * STAGE_F) * 4u;
        const uint32_t bs = as + (uint32_t)TILE_F * 4u;
        #pragma unroll
        for (int j = 0; j < 4; j++) {
            int row = srow + j * 32;        // 0..127
            cp16(as + (uint32_t)(row * LDS_ + sseg * 4) * 4u,
                 Abase + (size_t)row * GK + k0 + sseg * 4);
        }
        #pragma unroll
        for (int j = 0; j < 4; j++) {
            int row = srow + j * 32;
            cp16(bs + (uint32_t)(row * LDS_ + sseg * 4) * 4u,
                 Bbase + (size_t)row * GK + k0 + sseg * 4);
        }
        asm volatile("cp.async.commit_group;" ::: "memory");
    };

    issue_chunk(0, 0);
    issue_chunk(1, 1);

    for (int it = 0; it < NCHUNK; it++) {
        const int stg = it % NSTAGE;
        // Depth-aware drain: while another chunk is still in flight behind the
        // one we are about to consume, allow 1 pending group; on the tail
        // iteration require full drain (chunk `it` itself must have landed).
        if (it + 1 < NCHUNK) {
            asm volatile("cp.async.wait_group 1;" ::: "memory");
        } else {
            asm volatile("cp.async.wait_group 0;" ::: "memory");
        }
        __syncthreads();
        if (it + 2 < NCHUNK) issue_chunk(it + 2, (it + 2) % NSTAGE);

        const float* As = smem + stg * STAGE_F;
        const float* Bs = As + TILE_F;
        const float* Aw = As + (wm * 64 + lq) * LDS_ + lr;   // + mt*16*LDS_ + ks*8
        const float* Bw = Bs + (wn * 32 + lq) * LDS_ + lr;   // + nt*8*LDS_  + ks*8

        #pragma unroll
        for (int ks = 0; ks < 4; ks++) {
            uint32_t af[4][4], bf[4][2];
            #pragma unroll
            for (int mt = 0; mt < 4; mt++) {
                const float* p = Aw + mt * 16 * LDS_ + ks * 8;
                af[mt][0] = f2tfu(p[0]);
                af[mt][1] = f2tfu(p[8 * LDS_]);
                af[mt][2] = f2tfu(p[4]);
                af[mt][3] = f2tfu(p[8 * LDS_ + 4]);
            }
            #pragma unroll
            for (int nt = 0; nt < 4; nt++) {
                const float* p = Bw + nt * 8 * LDS_ + ks * 8;
                bf[nt][0] = f2tfu(p[0]);
                bf[nt][1] = f2tfu(p[4]);
            }
            #pragma unroll
            for (int mt = 0; mt < 4; mt++)
                #pragma unroll
                for (int nt = 0; nt < 4; nt++)
                    mma_tf32(acc[mt][nt], af[mt], bf[nt]);
        }
    }

    // epilogue: c0,c1 -> (row, col..col+1); c2,c3 -> (row+8, col..col+1)
    #pragma unroll
    for (int mt = 0; mt < 4; mt++) {
        int rg0 = row0 + wm*64 + mt*16 + lq;
        #pragma unroll
        for (int nt = 0; nt < 4; nt++) {
            int cg = col0 + wn*32 + nt*8 + lr*2;
            float2 bv = *(const float2*)&bias[cg];
            float s = (cg < scale_cols) ? scale : 1.f;
            float2 o0 = make_float2((acc[mt][nt][0] + bv.x) * s,
                                    (acc[mt][nt][1] + bv.y) * s);
            float2 o1 = make_float2((acc[mt][nt][2] + bv.x) * s,
                                    (acc[mt][nt][3] + bv.y) * s);
            *(float2*)&C[(size_t)rg0 * N + cg]       = o0;
            *(float2*)&C[(size_t)(rg0 + 8) * N + cg] = o1;
        }
    }
}

// ---------------------------------------------------------------------------
// Fused flash attention (main + ngram in one launch), BM=64 x BN=64, d=64.
// grid: (T/64, B*H, 3) — z=0: main (S=512), z=1,2: ngram n=z-1 (S=1024).
// ---------------------------------------------------------------------------
#define BM2 64
#define BN2 64
#define DP  68

__global__ __launch_bounds__(256) void attn_kernel(
    const float* __restrict__ qkv, const float* __restrict__ rel,
    const float* __restrict__ mask_main, const float* __restrict__ mask_ng,
    const int* __restrict__ ib_main, const int* __restrict__ ib_ng,
    float* __restrict__ ctx)
{
    extern __shared__ float sm[];
    float* sQt   = sm;                 // [64][DP]  Q^T (k-major)
    float* sK    = sQt + 64*DP;        // [64][DP]  K^T, later V[s][d]
    float* sP    = sK  + 64*DP;        // [64][DP]
    float* sRel  = sP  + 64*DP;        // [64][32]
    float* sM    = sRel + 64*32;
    float* sL    = sM + 64;
    float* sScale= sL + 64;

    const int bh = blockIdx.y;
    const int b  = bh >> 4;
    const int h  = bh & 15;
    const int z  = blockIdx.z;
    const int is_ng = (z > 0);
    const int n  = z - 1;
    const int t0 = blockIdx.x * BM2;
    const int S  = is_ng ? 1024 : 512;
    const int qtok0 = is_ng ? (T_ + n*T_ + t0) : t0;
    const float* maskrow = is_ng ? (mask_ng + (size_t)n * T_ * 1024) : mask_main;
    const int*   brow    = is_ng ? (ib_ng + (size_t)b * T_ * 1024)
                                 : (ib_main + (size_t)b * T_ * 512);

    const int tid = threadIdx.x;
    const int tx  = tid & 15, ty = tid >> 4;

    #pragma unroll
    for (int p = 0; p < 4; p++) {
        int idx = tid + p*256;
        int r  = idx >> 4;
        int c4 = (idx & 15) << 2;
        float4 v = *(const float4*)(qkv + (size_t)((qtok0 + r)*B_ + b)*3072 + h*D_ + c4);
        sQt[(c4+0)*DP + r] = v.x; sQt[(c4+1)*DP + r] = v.y;
        sQt[(c4+2)*DP + r] = v.z; sQt[(c4+3)*DP + r] = v.w;
    }
    #pragma unroll
    for (int p = 0; p < 8; p++) {
        int idx = tid + p*256;
        int r = idx >> 5, bk = idx & 31;
        sRel[r*32 + bk] = rel[(size_t)((qtok0 + r)*B_ + b)*512 + bk*H_ + h];
    }
    if (tid < 64) { sM[tid] = -1e30f; sL[tid] = 0.f; }

    ull accO[4][2];
    #pragma unroll
    for (int i = 0; i < 4; i++) { accO[i][0] = 0ull; accO[i][1] = 0ull; }

    for (int s0 = 0; s0 < S; s0 += BN2) {
        __syncthreads();
        #pragma unroll
        for (int p = 0; p < 4; p++) {
            int idx = tid + p*256;
            int sr = idx >> 4;
            int c4 = (idx & 15) << 2;
            int sg = s0 + sr;
            int tok = (!is_ng || sg < T_) ? sg : (T_ + n*T_ + (sg - T_));
            float4 v = *(const float4*)(qkv + (size_t)(tok*B_ + b)*3072 + 1024 + h*D_ + c4);
            sK[(c4+0)*DP + sr] = v.x; sK[(c4+1)*DP + sr] = v.y;
            sK[(c4+2)*DP + sr] = v.z; sK[(c4+3)*DP + sr] = v.w;
        }
        __syncthreads();

        ull acc[4][2];
        #pragma unroll
        for (int i = 0; i < 4; i++) { acc[i][0] = 0ull; acc[i][1] = 0ull; }
        #pragma unroll 8
        for (int kk = 0; kk < D_; kk++) {
            float4 a = *(const float4*)&sQt[kk*DP + ty*4];
            ull b0 = *(const ull*)&sK[kk*DP + tx*4];
            ull b1 = *(const ull*)&sK[kk*DP + tx*4 + 2];
            ull d;
            d = dup2(a.x); fma2(acc[0][0], d, b0); fma2(acc[0][1], d, b1);
            d = dup2(a.y); fma2(acc[1][0], d, b0); fma2(acc[1][1], d, b1);
            d = dup2(a.z); fma2(acc[2][0], d, b0); fma2(acc[2][1], d, b1);
            d = dup2(a.w); fma2(acc[3][0], d, b0); fma2(acc[3][1], d, b1);
        }
        #pragma unroll
        for (int i = 0; i < 4; i++) {
            int r  = ty*4 + i;
            int tg = t0 + r;
            const size_t base = (size_t)tg * S + s0 + tx*4;
            int4   bk = *(const int4*)&brow[base];
            float4 mk = *(const float4*)&maskrow[base];
            float2 v0 = unpack2(acc[i][0]);
            float2 v1 = unpack2(acc[i][1]);
            float4 o;
            o.x = v0.x + sRel[r*32 + bk.x] + mk.x;
            o.y = v0.y + sRel[r*32 + bk.y] + mk.y;
            o.z = v1.x + sRel[r*32 + bk.z] + mk.z;
            o.w = v1.y + sRel[r*32 + bk.w] + mk.w;
            *(float4*)&sP[r*DP + tx*4] = o;
        }
        __syncthreads();

        #pragma unroll
        for (int p = 0; p < 4; p++) {
            int idx = tid + p*256;
            int sr = idx >> 4;
            int c4 = (idx & 15) << 2;
            int sg = s0 + sr;
            int tok = (!is_ng || sg < T_) ? sg : (T_ + n*T_ + (sg - T_));
            float4 v = *(const float4*)(qkv + (size_t)(tok*B_ + b)*3072 + 2048 + h*D_ + c4);
            *(float4*)&sK[sr*DP + c4] = v;
        }

        {
            int r = tid >> 2, g = tid & 3;
            float* row = &sP[r*DP + g*16];
            float4 x0 = *(const float4*)(row);
            float4 x1 = *(const float4*)(row + 4);
            float4 x2 = *(const float4*)(row + 8);
            float4 x3 = *(const float4*)(row + 12);
            float mx = fmaxf(fmaxf(fmaxf(x0.x,x0.y),fmaxf(x0.z,x0.w)),
                      fmaxf(fmaxf(fmaxf(x1.x,x1.y),fmaxf(x1.z,x1.w)),
                      fmaxf(fmaxf(fmaxf(x2.x,x2.y),fmaxf(x2.z,x2.w)),
                            fmaxf(fmaxf(x3.x,x3.y),fmaxf(x3.z,x3.w)))));
            mx = fmaxf(mx, __shfl_xor_sync(0xffffffffu, mx, 1));
            mx = fmaxf(mx, __shfl_xor_sync(0xffffffffu, mx, 2));
            float oldm = sM[r];
            float newm = fmaxf(oldm, mx);
            x0.x = __expf(x0.x - newm); x0.y = __expf(x0.y - newm);
            x0.z = __expf(x0.z - newm); x0.w = __expf(x0.w - newm);
            x1.x = __expf(x1.x - newm); x1.y = __expf(x1.y - newm);
            x1.z = __expf(x1.z - newm); x1.w = __expf(x1.w - newm);
            x2.x = __expf(x2.x - newm); x2.y = __expf(x2.y - newm);
            x2.z = __expf(x2.z - newm); x2.w = __expf(x2.w - newm);
            x3.x = __expf(x3.x - newm); x3.y = __expf(x3.y - newm);
            x3.z = __expf(x3.z - newm); x3.w = __expf(x3.w - newm);
            float sum = (x0.x+x0.y+x0.z+x0.w) + (x1.x+x1.y+x1.z+x1.w)
                      + (x2.x+x2.y+x2.z+x2.w) + (x3.x+x3.y+x3.z+x3.w);
            sum += __shfl_xor_sync(0xffffffffu, sum, 1);
            sum += __shfl_xor_sync(0xffffffffu, sum, 2);
            *(float4*)(row)      = x0;
            *(float4*)(row + 4)  = x1;
            *(float4*)(row + 8)  = x2;
            *(float4*)(row + 12) = x3;
            if (g == 0) {
                float scl = __expf(oldm - newm);
                sScale[r] = scl;
                sL[r] = sL[r]*scl + sum;
                sM[r] = newm;
            }
        }
        __syncthreads();

        #pragma unroll
        for (int i = 0; i < 4; i++) {
            ull f = dup2(sScale[ty*4 + i]);
            accO[i][0] = mul2(accO[i][0], f);
            accO[i][1] = mul2(accO[i][1], f);
        }
        #pragma unroll 8
        for (int s = 0; s < BN2; s++) {
            ull v0 = *(const ull*)&sK[s*DP + tx*4];
            ull v1 = *(const ull*)&sK[s*DP + tx*4 + 2];
            ull p;
            p = dup2(sP[(ty*4+0)*DP + s]); fma2(accO[0][0], p, v0); fma2(accO[0][1], p, v1);
            p = dup2(sP[(ty*4+1)*DP + s]); fma2(accO[1][0], p, v0); fma2(accO[1][1], p, v1);
            p = dup2(sP[(ty*4+2)*DP + s]); fma2(accO[2][0], p, v0); fma2(accO[2][1], p, v1);
            p = dup2(sP[(ty*4+3)*DP + s]); fma2(accO[3][0], p, v0); fma2(accO[3][1], p, v1);
        }
    }

    #pragma unroll
    for (int i = 0; i < 4; i++) {
        int r = ty*4 + i;
        float inv = 1.f / sL[r];
        float2 a = unpack2(accO[i][0]);
        float2 c = unpack2(accO[i][1]);
        float4 o = make_float4(a.x*inv, a.y*inv, c.x*inv, c.y*inv);
        *(float4*)(ctx + (size_t)((qtok0 + r)*B_ + b)*1024 + h*D_ + tx*4) = o;
    }
}

#define SMEM_ATTN ((3*64*DP + 64*32 + 3*64) * 4)

// ---------------------------------------------------------------------------
extern "C" void kernel_launch(void* const* d_in, const int* in_sizes, int n_in,
                              void* d_out, int out_size)
{
    const float* hs        = (const float*)d_in[0];   // (1536,4,1024)
    const float* w_in      = (const float*)d_in[1];   // (3072,1024)
    const float* b_in      = (const float*)d_in[2];   // (3072,)
    const float* rw        = (const float*)d_in[3];   // (512,1024)
    const float* rb        = (const float*)d_in[4];   // (512,)
    const float* ow        = (const float*)d_in[5];   // (1024,1024)
    const float* ob        = (const float*)d_in[6];   // (1024,)
    const float* mask_main = (const float*)d_in[7];   // (512,512)
    const float* mask_ng   = (const float*)d_in[8];   // (2,512,1024)
    const int*   ib_main   = (const int*)d_in[9];     // (4,512,512)
    const int*   ib_ng     = (const int*)d_in[10];    // (4,512,1024)
    float* out = (float*)d_out;

    float *qkv, *rel, *ctx;
    cudaGetSymbolAddress((void**)&qkv, g_qkv);
    cudaGetSymbolAddress((void**)&rel, g_rel);
    cudaGetSymbolAddress((void**)&ctx, g_ctx);

    cudaFuncSetAttribute(gemm_mma, cudaFuncAttributeMaxDynamicSharedMemorySize, SMEM_GEMM);
    cudaFuncSetAttribute(attn_kernel, cudaFuncAttributeMaxDynamicSharedMemorySize, SMEM_ATTN);

    // QKV projection (tf32 mma.sync); q cols [0,1024) pre-scaled by 0.125
    gemm_mma<<<dim3(3072/128, ROWS_/128), 256, SMEM_GEMM>>>(
        hs, w_in, b_in, qkv, ROWS_, 3072, 1024, 0.125f);
    // rel-value table
    gemm_mma<<<dim3(512/128, ROWS_/128), 256, SMEM_GEMM>>>(
        hs, rw, rb, rel, ROWS_, 512, 0, 1.f);
    // fused attention: z=0 main, z=1,2 ngram
    attn_kernel<<<dim3(T_/BM2, B_*H_, 3), 256, SMEM_ATTN>>>(
        qkv, rel, mask_main, mask_ng, ib_main, ib_ng, ctx);
    // out projection directly into d_out
    gemm_mma<<<dim3(1024/128, ROWS_/128), 256, SMEM_GEMM>>>(
        ctx, ow, ob, out, ROWS_, 1024, 0, 1.f);
}

// round 14
// speedup vs baseline: 3.0773x; 1.5174x over previous
#include <cuda_runtime.h>
#include <cuda_bf16.h>
#include <cstdint>

#define T_ 512
#define B_ 4
#define H_ 16
#define D_ 64
#define NBKT 32
#define TOKENS 1536           // (1+NGRAM)*T
#define ROWS_ (TOKENS * B_)   // 6144
#define GK 1024               // K for all GEMMs
#define BK 32                 // K chunk
#define NCHUNK (GK / BK)      // 32
#define LDS_ 36               // smem row stride (floats): conflict-free frags
#define TILE_F (128 * LDS_)   // 4608 floats per tile
#define STAGE_F (2 * TILE_F)  // A tile + B tile per stage
#define NSTAGE 3
#define SMEM_GEMM (NSTAGE * STAGE_F * 4)   // 110592 B

typedef unsigned long long ull;

// Scratch (device globals: allocation-free rule)
__device__ float g_qkv[ROWS_ * 3072];  // q|k|v per row, q pre-scaled by 1/8
__device__ float g_rel[ROWS_ * 512];   // rel-value table, col = bucket*16 + head
__device__ float g_ctx[ROWS_ * 1024];  // attention output pre out-proj

// ---- tf32 helpers (arch-generic: sm_80+) ----
__device__ __forceinline__ uint32_t f2tfu(float f) {
    uint32_t r; asm("cvt.rna.tf32.f32 %0, %1;" : "=r"(r) : "f"(f));
    return r;
}
__device__ __forceinline__ void mma_tf32(float* c, const uint32_t* a, const uint32_t* b) {
    asm volatile(
        "mma.sync.aligned.m16n8k8.row.col.f32.tf32.tf32.f32 "
        "{%0,%1,%2,%3}, {%4,%5,%6,%7}, {%8,%9}, {%0,%1,%2,%3};"
        : "+f"(c[0]), "+f"(c[1]), "+f"(c[2]), "+f"(c[3])
        : "r"(a[0]), "r"(a[1]), "r"(a[2]), "r"(a[3]), "r"(b[0]), "r"(b[1]));
}
// ---- bf16 helpers ----
__device__ __forceinline__ void mma_bf16(float* c, const uint32_t* a, const uint32_t* b) {
    asm volatile(
        "mma.sync.aligned.m16n8k16.row.col.f32.bf16.bf16.f32 "
        "{%0,%1,%2,%3}, {%4,%5,%6,%7}, {%8,%9}, {%0,%1,%2,%3};"
        : "+f"(c[0]), "+f"(c[1]), "+f"(c[2]), "+f"(c[3])
        : "r"(a[0]), "r"(a[1]), "r"(a[2]), "r"(a[3]), "r"(b[0]), "r"(b[1]));
}
// pack two floats to bf16x2: elem0 -> low half (k even), elem1 -> high half
__device__ __forceinline__ uint32_t bf2(float e0, float e1) {
    uint32_t r; asm("cvt.rn.bf16x2.f32 %0, %1, %2;" : "=r"(r) : "f"(e1), "f"(e0));
    return r;
}
// split (x,y) into hi-packed bf16x2 and residual-packed bf16x2
__device__ __forceinline__ void bfsplit2(float x, float y, uint32_t& uh, uint32_t& ul) {
    uh = bf2(x, y);
    float hx = __uint_as_float((uh & 0xffffu) << 16);
    float hy = __uint_as_float(uh & 0xffff0000u);
    ul = bf2(x - hx, y - hy);
}
__device__ __forceinline__ uint32_t smem_u32(const void* p) {
    uint32_t a;
    asm("{ .reg .u64 t; cvta.to.shared.u64 t, %1; cvt.u32.u64 %0, t; }" : "=r"(a) : "l"(p));
    return a;
}
__device__ __forceinline__ void cp16(uint32_t dst, const void* src) {
    asm volatile("cp.async.ca.shared.global [%0], [%1], 16;" :: "r"(dst), "l"(src));
}

// ---------------------------------------------------------------------------
// tf32 mma.sync GEMM (verified correct+fast in round 8: ~105 TF/s)
// ---------------------------------------------------------------------------
__global__ __launch_bounds__(256, 2) void gemm_mma(
    const float* __restrict__ A, const float* __restrict__ Bm,
    const float* __restrict__ bias, float* __restrict__ C,
    int M, int N, int scale_cols, float scale)
{
    extern __shared__ float smem[];
    const uint32_t sb = smem_u32(smem);

    const int tid  = threadIdx.x;
    const int wid  = tid >> 5;
    const int lane = tid & 31;
    const int row0 = blockIdx.y * 128;
    const int col0 = blockIdx.x * 128;
    const int wm   = wid >> 2;
    const int wn   = wid & 3;
    const int lq   = lane >> 2;
    const int lr   = lane & 3;
    const int srow = tid >> 3;
    const int sseg = tid & 7;

    float acc[4][4][4];
    #pragma unroll
    for (int i = 0; i < 4; i++)
        #pragma unroll
        for (int j = 0; j < 4; j++)
            #pragma unroll
            for (int q = 0; q < 4; q++) acc[i][j][q] = 0.f;

    const float* Abase = A  + (size_t)row0 * GK;
    const float* Bbase = Bm + (size_t)col0 * GK;

    auto issue_chunk = [&](int chunk, int stg) {
        const int k0 = chunk * BK;
        const uint32_t as = sb + (uint32_t)(stg * STAGE_F) * 4u;
        const uint32_t bs = as + (uint32_t)TILE_F * 4u;
        #pragma unroll
        for (int j = 0; j < 4; j++) {
            int row = srow + j * 32;
            cp16(as + (uint32_t)(row * LDS_ + sseg * 4) * 4u,
                 Abase + (size_t)row * GK + k0 + sseg * 4);
        }
        #pragma unroll
        for (int j = 0; j < 4; j++) {
            int row = srow + j * 32;
            cp16(bs + (uint32_t)(row * LDS_ + sseg * 4) * 4u,
                 Bbase + (size_t)row * GK + k0 + sseg * 4);
        }
        asm volatile("cp.async.commit_group;" ::: "memory");
    };

    issue_chunk(0, 0);
    issue_chunk(1, 1);

    for (int it = 0; it < NCHUNK; it++) {
        const int stg = it % NSTAGE;
        if (it + 1 < NCHUNK) {
            asm volatile("cp.async.wait_group 1;" ::: "memory");
        } else {
            asm volatile("cp.async.wait_group 0;" ::: "memory");
        }
        __syncthreads();
        if (it + 2 < NCHUNK) issue_chunk(it + 2, (it + 2) % NSTAGE);

        const float* As = smem + stg * STAGE_F;
        const float* Bs = As + TILE_F;
        const float* Aw = As + (wm * 64 + lq) * LDS_ + lr;
        const float* Bw = Bs + (wn * 32 + lq) * LDS_ + lr;

        #pragma unroll
        for (int ks = 0; ks < 4; ks++) {
            uint32_t af[4][4], bf[4][2];
            #pragma unroll
            for (int mt = 0; mt < 4; mt++) {
                const float* p = Aw + mt * 16 * LDS_ + ks * 8;
                af[mt][0] = f2tfu(p[0]);
                af[mt][1] = f2tfu(p[8 * LDS_]);
                af[mt][2] = f2tfu(p[4]);
                af[mt][3] = f2tfu(p[8 * LDS_ + 4]);
            }
            #pragma unroll
            for (int nt = 0; nt < 4; nt++) {
                const float* p = Bw + nt * 8 * LDS_ + ks * 8;
                bf[nt][0] = f2tfu(p[0]);
                bf[nt][1] = f2tfu(p[4]);
            }
            #pragma unroll
            for (int mt = 0; mt < 4; mt++)
                #pragma unroll
                for (int nt = 0; nt < 4; nt++)
                    mma_tf32(acc[mt][nt], af[mt], bf[nt]);
        }
    }

    #pragma unroll
    for (int mt = 0; mt < 4; mt++) {
        int rg0 = row0 + wm*64 + mt*16 + lq;
        #pragma unroll
        for (int nt = 0; nt < 4; nt++) {
            int cg = col0 + wn*32 + nt*8 + lr*2;
            float2 bv = *(const float2*)&bias[cg];
            float s = (cg < scale_cols) ? scale : 1.f;
            float2 o0 = make_float2((acc[mt][nt][0] + bv.x) * s,
                                    (acc[mt][nt][1] + bv.y) * s);
            float2 o1 = make_float2((acc[mt][nt][2] + bv.x) * s,
                                    (acc[mt][nt][3] + bv.y) * s);
            *(float2*)&C[(size_t)rg0 * N + cg]       = o0;
            *(float2*)&C[(size_t)(rg0 + 8) * N + cg] = o1;
        }
    }
}

// ---------------------------------------------------------------------------
// Tensor-core attention: split-bf16 3-term mma for QK^T and PV.
// BM=64 q-rows, BN=128 keys per iter, 256 threads (8 warps).
// Scores: 2x4 warp grid of 32x32 tiles. PV: 2 s-half groups x (2x2 of 32x32).
// Mask-aware tile skipping (causal + ngram diagonal).
// grid: (T/64, B*H, 3) — z=0: main (S=512), z=1,2: ngram n=z-1 (S=1024).
// ---------------------------------------------------------------------------
// smem offsets (floats): QHI 0, QLO 2304, KHI 4608, KLO 9216, VHI 13824,
// VLO 18176, SS 22528 ([64][132]), PHI 30976, PLO 35328, REL 39680,
// SM 41728, SL 41792, SSC 41856; total 41920 floats = 167680 B
#define AT_QHI 0
#define AT_QLO 2304
#define AT_KHI 4608
#define AT_KLO 9216
#define AT_VHI 13824
#define AT_VLO 18176
#define AT_SS  22528
#define AT_PHI 30976
#define AT_PLO 35328
#define AT_REL 39680
#define AT_SM  41728
#define AT_SL  41792
#define AT_SSC 41856
#define SMEM_ATTN (41920 * 4)

__global__ __launch_bounds__(256, 1) void attn_mma(
    const float* __restrict__ qkv, const float* __restrict__ rel,
    const float* __restrict__ mask_main, const float* __restrict__ mask_ng,
    const int* __restrict__ ib_main, const int* __restrict__ ib_ng,
    float* __restrict__ ctx)
{
    extern __shared__ float sm_[];
    uint32_t* uQh = (uint32_t*)(sm_ + AT_QHI);
    uint32_t* uQl = (uint32_t*)(sm_ + AT_QLO);
    uint32_t* uKh = (uint32_t*)(sm_ + AT_KHI);
    uint32_t* uKl = (uint32_t*)(sm_ + AT_KLO);
    uint32_t* uVh = (uint32_t*)(sm_ + AT_VHI);
    uint32_t* uVl = (uint32_t*)(sm_ + AT_VLO);
    float*    sS  = sm_ + AT_SS;      // [64][132]
    uint32_t* uPh = (uint32_t*)(sm_ + AT_PHI);   // [64][68]
    uint32_t* uPl = (uint32_t*)(sm_ + AT_PLO);
    float*    sRel= sm_ + AT_REL;     // [64][32]
    float*    sM  = sm_ + AT_SM;
    float*    sL  = sm_ + AT_SL;
    float*    sSc = sm_ + AT_SSC;

    const int bh = blockIdx.y;
    const int b  = bh >> 4;
    const int h  = bh & 15;
    const int z  = blockIdx.z;
    const int is_ng = (z > 0);
    const int n  = z - 1;
    const int t0 = blockIdx.x * 64;
    const int S  = is_ng ? 1024 : 512;
    const int qtok0 = is_ng ? (T_ + n*T_ + t0) : t0;
    const float* maskrow = is_ng ? (mask_ng + (size_t)n * T_ * 1024) : mask_main;
    const int*   brow    = is_ng ? (ib_ng + (size_t)b * T_ * 1024)
                                 : (ib_main + (size_t)b * T_ * 512);

    const int tid  = threadIdx.x;
    const int wid  = tid >> 5;
    const int lane = tid & 31;
    const int lq   = lane >> 2;
    const int lr   = lane & 3;

    // ---- load Q (hi/lo split), rel LUT, init stats ----
    #pragma unroll
    for (int p = 0; p < 4; p++) {
        int idx = tid + p*256;                    // 64 rows x 16 float4
        int r  = idx >> 4;
        int c4 = (idx & 15) << 2;
        float4 v = *(const float4*)(qkv + (size_t)((qtok0 + r)*B_ + b)*3072 + h*D_ + c4);
        uint32_t h0, l0, h1, l1;
        bfsplit2(v.x, v.y, h0, l0);
        bfsplit2(v.z, v.w, h1, l1);
        uQh[r*36 + (c4>>1)]     = h0;  uQh[r*36 + (c4>>1) + 1] = h1;
        uQl[r*36 + (c4>>1)]     = l0;  uQl[r*36 + (c4>>1) + 1] = l1;
    }
    #pragma unroll
    for (int p = 0; p < 8; p++) {
        int idx = tid + p*256;
        int r = idx >> 5, bk = idx & 31;
        sRel[r*32 + bk] = rel[(size_t)((qtok0 + r)*B_ + b)*512 + bk*H_ + h];
    }
    if (tid < 64) { sM[tid] = -1e30f; sL[tid] = 0.f; }

    float accO[2][4][4];
    #pragma unroll
    for (int mt = 0; mt < 2; mt++)
        #pragma unroll
        for (int nt = 0; nt < 4; nt++)
            #pragma unroll
            for (int q = 0; q < 4; q++) accO[mt][nt][q] = 0.f;

    const int wm2 = wid >> 2;          // scores: 0..1 (m)
    const int wn2 = wid & 3;           // scores: 0..3 (n)
    const int grp = wid >> 2;          // PV: s-half
    const int wmo = (wid >> 1) & 1;    // PV: O row tile
    const int wno = wid & 1;           // PV: O col tile

    for (int s0 = 0; s0 < S; s0 += 128) {
        // mask-aware tile skip (uniform across CTA — no divergent barriers)
        bool keep;
        if (!is_ng || s0 < 512) keep = (s0 <= t0 + 63);
        else { int d = s0 - 512; keep = (d > t0 - 128) && (d < t0 + 64); }
        if (!keep) continue;

        __syncthreads();   // prev PV done with K/V/P buffers; iter0: Q/rel ready

        // ---- K (hi/lo, [s][dpair]) and V^T (hi/lo, [d][spair]) ----
        #pragma unroll
        for (int p = 0; p < 8; p++) {
            int idx = tid + p*256;                // 128 rows x 16 float4
            int sr = idx >> 4;
            int c4 = (idx & 15) << 2;
            int sg = s0 + sr;
            int tok = (!is_ng || sg < T_) ? sg : (T_ + n*T_ + (sg - T_));
            float4 v = *(const float4*)(qkv + (size_t)(tok*B_ + b)*3072 + 1024 + h*D_ + c4);
            uint32_t h0, l0, h1, l1;
            bfsplit2(v.x, v.y, h0, l0);
            bfsplit2(v.z, v.w, h1, l1);
            uKh[sr*36 + (c4>>1)]     = h0;  uKh[sr*36 + (c4>>1) + 1] = h1;
            uKl[sr*36 + (c4>>1)]     = l0;  uKl[sr*36 + (c4>>1) + 1] = l1;
        }
        #pragma unroll
        for (int p = 0; p < 4; p++) {
            int idx = tid + p*256;                // 64 spairs x 16 d-groups
            int j  = idx & 63;                    // spair
            int d4 = (idx >> 6) << 2;
            int sg0 = s0 + 2*j, sg1 = sg0 + 1;
            int tok0 = (!is_ng || sg0 < T_) ? sg0 : (T_ + n*T_ + (sg0 - T_));
            int tok1 = (!is_ng || sg1 < T_) ? sg1 : (T_ + n*T_ + (sg1 - T_));
            float4 v0 = *(const float4*)(qkv + (size_t)(tok0*B_ + b)*3072 + 2048 + h*D_ + d4);
            float4 v1 = *(const float4*)(qkv + (size_t)(tok1*B_ + b)*3072 + 2048 + h*D_ + d4);
            const float e0[4] = {v0.x, v0.y, v0.z, v0.w};
            const float e1[4] = {v1.x, v1.y, v1.z, v1.w};
            #pragma unroll
            for (int i = 0; i < 4; i++) {
                uint32_t hh, ll;
                bfsplit2(e0[i], e1[i], hh, ll);
                uVh[(d4 + i)*68 + j] = hh;
                uVl[(d4 + i)*68 + j] = ll;
            }
        }
        __syncthreads();

        // ---- scores: 3-term bf16 mma (hi*hi + hi*lo + lo*hi) ----
        float acc[2][4][4];
        #pragma unroll
        for (int mt = 0; mt < 2; mt++)
            #pragma unroll
            for (int nt = 0; nt < 4; nt++)
                #pragma unroll
                for (int q = 0; q < 4; q++) acc[mt][nt][q] = 0.f;

        #pragma unroll
        for (int ks = 0; ks < 4; ks++) {
            uint32_t ah[2][4], al[2][4], bhv[4][2], blv[4][2];
            #pragma unroll
            for (int mt = 0; mt < 2; mt++) {
                int m = wm2*32 + mt*16 + lq;
                const uint32_t* p = uQh + m*36 + ks*8 + lr;
                ah[mt][0] = p[0]; ah[mt][1] = p[8*36]; ah[mt][2] = p[4]; ah[mt][3] = p[8*36+4];
                const uint32_t* q2 = uQl + m*36 + ks*8 + lr;
                al[mt][0] = q2[0]; al[mt][1] = q2[8*36]; al[mt][2] = q2[4]; al[mt][3] = q2[8*36+4];
            }
            #pragma unroll
            for (int nt = 0; nt < 4; nt++) {
                int nn = wn2*32 + nt*8 + lq;
                const uint32_t* p = uKh + nn*36 + ks*8 + lr;
                bhv[nt][0] = p[0]; bhv[nt][1] = p[4];
                const uint32_t* q2 = uKl + nn*36 + ks*8 + lr;
                blv[nt][0] = q2[0]; blv[nt][1] = q2[4];
            }
            #pragma unroll
            for (int mt = 0; mt < 2; mt++)
                #pragma unroll
                for (int nt = 0; nt < 4; nt++) {
                    mma_bf16(acc[mt][nt], ah[mt], bhv[nt]);
                    mma_bf16(acc[mt][nt], ah[mt], blv[nt]);
                    mma_bf16(acc[mt][nt], al[mt], bhv[nt]);
                }
        }

        // + rel(bucket) + mask -> sS
        #pragma unroll
        for (int mt = 0; mt < 2; mt++) {
            int r0 = wm2*32 + mt*16 + lq, r1 = r0 + 8;
            int tg0 = t0 + r0, tg1 = t0 + r1;
            #pragma unroll
            for (int nt = 0; nt < 4; nt++) {
                int col = wn2*32 + nt*8 + 2*lr;
                int sg  = s0 + col;
                int2   bk0 = *(const int2*)&brow[(size_t)tg0 * S + sg];
                float2 mk0 = *(const float2*)&maskrow[(size_t)tg0 * S + sg];
                float2 o0 = make_float2(acc[mt][nt][0] + sRel[r0*32 + bk0.x] + mk0.x,
                                        acc[mt][nt][1] + sRel[r0*32 + bk0.y] + mk0.y);
                *(float2*)&sS[r0*132 + col] = o0;
                int2   bk1 = *(const int2*)&brow[(size_t)tg1 * S + sg];
                float2 mk1 = *(const float2*)&maskrow[(size_t)tg1 * S + sg];
                float2 o1 = make_float2(acc[mt][nt][2] + sRel[r1*32 + bk1.x] + mk1.x,
                                        acc[mt][nt][3] + sRel[r1*32 + bk1.y] + mk1.y);
                *(float2*)&sS[r1*132 + col] = o1;
            }
        }
        __syncthreads();

        // ---- softmax (4 threads/row, 32 cols each) + pack P hi/lo ----
        {
            int r = tid >> 2, g = tid & 3;
            float* row = sS + r*132 + g*32;
            float x[32];
            #pragma unroll
            for (int i = 0; i < 8; i++) {
                float4 v = *(const float4*)(row + i*4);
                x[i*4+0] = v.x; x[i*4+1] = v.y; x[i*4+2] = v.z; x[i*4+3] = v.w;
            }
            float mx = -1e30f;
            #pragma unroll
            for (int i = 0; i < 32; i++) mx = fmaxf(mx, x[i]);
            mx = fmaxf(mx, __shfl_xor_sync(0xffffffffu, mx, 1));
            mx = fmaxf(mx, __shfl_xor_sync(0xffffffffu, mx, 2));
            float oldm = sM[r];
            float newm = fmaxf(oldm, mx);
            float sum = 0.f;
            #pragma unroll
            for (int i = 0; i < 32; i++) { x[i] = __expf(x[i] - newm); sum += x[i]; }
            sum += __shfl_xor_sync(0xffffffffu, sum, 1);
            sum += __shfl_xor_sync(0xffffffffu, sum, 2);
            #pragma unroll
            for (int i = 0; i < 16; i++) {
                uint32_t hh, ll;
                bfsplit2(x[2*i], x[2*i+1], hh, ll);
                uPh[r*68 + g*16 + i] = hh;
                uPl[r*68 + g*16 + i] = ll;
            }
            if (g == 0) {
                float scl = __expf(oldm - newm);
                sSc[r] = scl;
                sL[r] = sL[r]*scl + sum;
                sM[r] = newm;
            }
        }
        __syncthreads();

        // ---- PV: rescale accO, then 3-term bf16 mma over this s-half ----
        #pragma unroll
        for (int mt = 0; mt < 2; mt++) {
            float s0r = sSc[wmo*32 + mt*16 + lq];
            float s1r = sSc[wmo*32 + mt*16 + lq + 8];
            #pragma unroll
            for (int nt = 0; nt < 4; nt++) {
                accO[mt][nt][0] *= s0r; accO[mt][nt][1] *= s0r;
                accO[mt][nt][2] *= s1r; accO[mt][nt][3] *= s1r;
            }
        }
        #pragma unroll
        for (int ks = 0; ks < 4; ks++) {
            int kp = grp*32 + ks*8 + lr;      // spair index
            uint32_t ah[2][4], al[2][4], bhv[4][2], blv[4][2];
            #pragma unroll
            for (int mt = 0; mt < 2; mt++) {
                int m = wmo*32 + mt*16 + lq;
                const uint32_t* p = uPh + m*68 + kp;
                ah[mt][0] = p[0]; ah[mt][1] = p[8*68]; ah[mt][2] = p[4]; ah[mt][3] = p[8*68+4];
                const uint32_t* q2 = uPl + m*68 + kp;
                al[mt][0] = q2[0]; al[mt][1] = q2[8*68]; al[mt][2] = q2[4]; al[mt][3] = q2[8*68+4];
            }
            #pragma unroll
            for (int nt = 0; nt < 4; nt++) {
                int nn = wno*32 + nt*8 + lq;
                const uint32_t* p = uVh + nn*68 + kp;
                bhv[nt][0] = p[0]; bhv[nt][1] = p[4];
                const uint32_t* q2 = uVl + nn*68 + kp;
                blv[nt][0] = q2[0]; blv[nt][1] = q2[4];
            }
            #pragma unroll
            for (int mt = 0; mt < 2; mt++)
                #pragma unroll
                for (int nt = 0; nt < 4; nt++) {
                    mma_bf16(accO[mt][nt], ah[mt], bhv[nt]);
                    mma_bf16(accO[mt][nt], ah[mt], blv[nt]);
                    mma_bf16(accO[mt][nt], al[mt], bhv[nt]);
                }
        }
    }

    // ---- epilogue: reduce the two s-half groups, normalize, write ----
    __syncthreads();
    float* sRed = sS;     // reuse as [64][68]
    if (wid >= 4) {
        #pragma unroll
        for (int mt = 0; mt < 2; mt++) {
            int r0 = wmo*32 + mt*16 + lq, r1 = r0 + 8;
            #pragma unroll
            for (int nt = 0; nt < 4; nt++) {
                int col = wno*32 + nt*8 + 2*lr;
                *(float2*)&sRed[r0*68 + col] = make_float2(accO[mt][nt][0], accO[mt][nt][1]);
                *(float2*)&sRed[r1*68 + col] = make_float2(accO[mt][nt][2], accO[mt][nt][3]);
            }
        }
    }
    __syncthreads();
    if (wid < 4) {
        #pragma unroll
        for (int mt = 0; mt < 2; mt++) {
            int r0 = wmo*32 + mt*16 + lq, r1 = r0 + 8;
            float inv0 = 1.f / sL[r0];
            float inv1 = 1.f / sL[r1];
            #pragma unroll
            for (int nt = 0; nt < 4; nt++) {
                int col = wno*32 + nt*8 + 2*lr;
                float2 q0 = *(const float2*)&sRed[r0*68 + col];
                float2 q1 = *(const float2*)&sRed[r1*68 + col];
                float2 o0 = make_float2((accO[mt][nt][0] + q0.x) * inv0,
                                        (accO[mt][nt][1] + q0.y) * inv0);
                float2 o1 = make_float2((accO[mt][nt][2] + q1.x) * inv1,
                                        (accO[mt][nt][3] + q1.y) * inv1);
                *(float2*)(ctx + (size_t)((qtok0 + r0)*B_ + b)*1024 + h*D_ + col) = o0;
                *(float2*)(ctx + (size_t)((qtok0 + r1)*B_ + b)*1024 + h*D_ + col) = o1;
            }
        }
    }
}

// ---------------------------------------------------------------------------
extern "C" void kernel_launch(void* const* d_in, const int* in_sizes, int n_in,
                              void* d_out, int out_size)
{
    const float* hs        = (const float*)d_in[0];   // (1536,4,1024)
    const float* w_in      = (const float*)d_in[1];   // (3072,1024)
    const float* b_in      = (const float*)d_in[2];   // (3072,)
    const float* rw        = (const float*)d_in[3];   // (512,1024)
    const float* rb        = (const float*)d_in[4];   // (512,)
    const float* ow        = (const float*)d_in[5];   // (1024,1024)
    const float* ob        = (const float*)d_in[6];   // (1024,)
    const float* mask_main = (const float*)d_in[7];   // (512,512)
    const float* mask_ng   = (const float*)d_in[8];   // (2,512,1024)
    const int*   ib_main   = (const int*)d_in[9];     // (4,512,512)
    const int*   ib_ng     = (const int*)d_in[10];    // (4,512,1024)
    float* out = (float*)d_out;

    float *qkv, *rel, *ctx;
    cudaGetSymbolAddress((void**)&qkv, g_qkv);
    cudaGetSymbolAddress((void**)&rel, g_rel);
    cudaGetSymbolAddress((void**)&ctx, g_ctx);

    cudaFuncSetAttribute(gemm_mma, cudaFuncAttributeMaxDynamicSharedMemorySize, SMEM_GEMM);
    cudaFuncSetAttribute(attn_mma, cudaFuncAttributeMaxDynamicSharedMemorySize, SMEM_ATTN);

    // QKV projection (tf32 mma.sync); q cols [0,1024) pre-scaled by 0.125
    gemm_mma<<<dim3(3072/128, ROWS_/128), 256, SMEM_GEMM>>>(
        hs, w_in, b_in, qkv, ROWS_, 3072, 1024, 0.125f);
    // rel-value table
    gemm_mma<<<dim3(512/128, ROWS_/128), 256, SMEM_GEMM>>>(
        hs, rw, rb, rel, ROWS_, 512, 0, 1.f);
    // fused attention (tensor cores): z=0 main, z=1,2 ngram
    attn_mma<<<dim3(T_/64, B_*H_, 3), 256, SMEM_ATTN>>>(
        qkv, rel, mask_main, mask_ng, ib_main, ib_ng, ctx);
    // out projection directly into d_out
    gemm_mma<<<dim3(1024/128, ROWS_/128), 256, SMEM_GEMM>>>(
        ctx, ow, ob, out, ROWS_, 1024, 0, 1.f);
}

// round 15
// speedup vs baseline: 3.2850x; 1.0675x over previous
#include <cuda_runtime.h>
#include <cuda_bf16.h>
#include <cstdint>

#define T_ 512
#define B_ 4
#define H_ 16
#define D_ 64
#define NBKT 32
#define TOKENS 1536           // (1+NGRAM)*T
#define ROWS_ (TOKENS * B_)   // 6144
#define GK 1024               // K for all GEMMs
#define BK 32                 // K chunk
#define NCHUNK (GK / BK)      // 32
#define LDS_ 36               // smem row stride (floats): conflict-free frags
#define TILE_F (128 * LDS_)   // 4608 floats per tile
#define STAGE_F (2 * TILE_F)  // A tile + B tile per stage
#define NSTAGE 3
#define SMEM_GEMM (NSTAGE * STAGE_F * 4)   // 110592 B
#define NCAT 3584             // fused qkv(3072) + rel(512) output cols

typedef unsigned long long ull;

// Scratch (device globals: allocation-free rule)
__device__ float g_qkv[ROWS_ * 3072];   // q|k|v per row, q pre-scaled by 1/8
__device__ float g_rel[ROWS_ * 512];    // rel-value table, col = bucket*16 + head
__device__ float g_ctx[ROWS_ * 1024];   // attention out (tf32-rounded), pre out-proj
__device__ float g_hs_tf[ROWS_ * 1024]; // hs pre-rounded to tf32
__device__ float g_wcat[NCAT * 1024];   // [w_in; rel_w] pre-rounded to tf32
__device__ float g_owt[1024 * 1024];    // out_w pre-rounded to tf32
__device__ float g_bcat[NCAT];          // [b_in; rel_b]

// ---- tf32 helpers (arch-generic: sm_80+) ----
__device__ __forceinline__ uint32_t f2tfu(float f) {
    uint32_t r; asm("cvt.rna.tf32.f32 %0, %1;" : "=r"(r) : "f"(f));
    return r;
}
__device__ __forceinline__ void mma_tf32(float* c, const uint32_t* a, const uint32_t* b) {
    asm volatile(
        "mma.sync.aligned.m16n8k8.row.col.f32.tf32.tf32.f32 "
        "{%0,%1,%2,%3}, {%4,%5,%6,%7}, {%8,%9}, {%0,%1,%2,%3};"
        : "+f"(c[0]), "+f"(c[1]), "+f"(c[2]), "+f"(c[3])
        : "r"(a[0]), "r"(a[1]), "r"(a[2]), "r"(a[3]), "r"(b[0]), "r"(b[1]));
}
// ---- bf16 helpers ----
__device__ __forceinline__ void mma_bf16(float* c, const uint32_t* a, const uint32_t* b) {
    asm volatile(
        "mma.sync.aligned.m16n8k16.row.col.f32.bf16.bf16.f32 "
        "{%0,%1,%2,%3}, {%4,%5,%6,%7}, {%8,%9}, {%0,%1,%2,%3};"
        : "+f"(c[0]), "+f"(c[1]), "+f"(c[2]), "+f"(c[3])
        : "r"(a[0]), "r"(a[1]), "r"(a[2]), "r"(a[3]), "r"(b[0]), "r"(b[1]));
}
__device__ __forceinline__ uint32_t bf2(float e0, float e1) {
    uint32_t r; asm("cvt.rn.bf16x2.f32 %0, %1, %2;" : "=r"(r) : "f"(e1), "f"(e0));
    return r;
}
__device__ __forceinline__ void bfsplit2(float x, float y, uint32_t& uh, uint32_t& ul) {
    uh = bf2(x, y);
    float hx = __uint_as_float((uh & 0xffffu) << 16);
    float hy = __uint_as_float(uh & 0xffff0000u);
    ul = bf2(x - hx, y - hy);
}
__device__ __forceinline__ uint32_t smem_u32(const void* p) {
    uint32_t a;
    asm("{ .reg .u64 t; cvta.to.shared.u64 t, %1; cvt.u32.u64 %0, t; }" : "=r"(a) : "l"(p));
    return a;
}
__device__ __forceinline__ void cp16(uint32_t dst, const void* src) {
    asm volatile("cp.async.ca.shared.global [%0], [%1], 16;" :: "r"(dst), "l"(src));
}

// ---------------------------------------------------------------------------
// Elementwise tf32 pre-rounding (vectorized float4)
// ---------------------------------------------------------------------------
__global__ __launch_bounds__(256) void cvt_tf32(
    const float* __restrict__ src, float* __restrict__ dst, int n4)
{
    int i = blockIdx.x * 256 + threadIdx.x;
    if (i < n4) {
        float4 v = ((const float4*)src)[i];
        v.x = __uint_as_float(f2tfu(v.x));
        v.y = __uint_as_float(f2tfu(v.y));
        v.z = __uint_as_float(f2tfu(v.z));
        v.w = __uint_as_float(f2tfu(v.w));
        ((float4*)dst)[i] = v;
    }
}

// ---------------------------------------------------------------------------
// GEMM mainloop macro (inputs pre-rounded to tf32 -> pure LDS + MMA)
// Defines/fills: acc[4][4][4]. Uses: A_, B_ (row-major, K=1024), sb/smem, ids.
// ---------------------------------------------------------------------------
#define GEMM_MAINLOOP(Abase, Bbase)                                            \
    float acc[4][4][4];                                                        \
    _Pragma("unroll")                                                          \
    for (int i = 0; i < 4; i++)                                                \
        _Pragma("unroll")                                                      \
        for (int j = 0; j < 4; j++)                                            \
            _Pragma("unroll")                                                  \
            for (int q = 0; q < 4; q++) acc[i][j][q] = 0.f;                    \
    auto issue_chunk = [&](int chunk, int stg) {                               \
        const int k0 = chunk * BK;                                             \
        const uint32_t as = sb + (uint32_t)(stg * STAGE_F) * 4u;               \
        const uint32_t bs = as + (uint32_t)TILE_F * 4u;                        \
        _Pragma("unroll")                                                      \
        for (int j = 0; j < 4; j++) {                                          \
            int row = srow + j * 32;                                           \
            cp16(as + (uint32_t)(row * LDS_ + sseg * 4) * 4u,                  \
                 Abase + (size_t)row * GK + k0 + sseg * 4);                    \
        }                                                                      \
        _Pragma("unroll")                                                      \
        for (int j = 0; j < 4; j++) {                                          \
            int row = srow + j * 32;                                           \
            cp16(bs + (uint32_t)(row * LDS_ + sseg * 4) * 4u,                  \
                 Bbase + (size_t)row * GK + k0 + sseg * 4);                    \
        }                                                                      \
        asm volatile("cp.async.commit_group;" ::: "memory");                   \
    };                                                                         \
    issue_chunk(0, 0);                                                         \
    issue_chunk(1, 1);                                                         \
    for (int it = 0; it < NCHUNK; it++) {                                      \
        const int stg = it % NSTAGE;                                           \
        if (it + 1 < NCHUNK) {                                                 \
            asm volatile("cp.async.wait_group 1;" ::: "memory");               \
        } else {                                                               \
            asm volatile("cp.async.wait_group 0;" ::: "memory");               \
        }                                                                      \
        __syncthreads();                                                       \
        if (it + 2 < NCHUNK) issue_chunk(it + 2, (it + 2) % NSTAGE);           \
        const uint32_t* As = (const uint32_t*)(smem + stg * STAGE_F);          \
        const uint32_t* Bs = As + TILE_F;                                      \
        const uint32_t* Aw = As + (wm * 64 + lq) * LDS_ + lr;                  \
        const uint32_t* Bw = Bs + (wn * 32 + lq) * LDS_ + lr;                  \
        _Pragma("unroll")                                                      \
        for (int ks = 0; ks < 4; ks++) {                                       \
            uint32_t af[4][4], bf[4][2];                                       \
            _Pragma("unroll")                                                  \
            for (int mt = 0; mt < 4; mt++) {                                   \
                const uint32_t* p = Aw + mt * 16 * LDS_ + ks * 8;              \
                af[mt][0] = p[0];                                              \
                af[mt][1] = p[8 * LDS_];                                       \
                af[mt][2] = p[4];                                              \
                af[mt][3] = p[8 * LDS_ + 4];                                   \
            }                                                                  \
            _Pragma("unroll")                                                  \
            for (int nt = 0; nt < 4; nt++) {                                   \
                const uint32_t* p = Bw + nt * 8 * LDS_ + ks * 8;               \
                bf[nt][0] = p[0];                                              \
                bf[nt][1] = p[4];                                              \
            }                                                                  \
            _Pragma("unroll")                                                  \
            for (int mt = 0; mt < 4; mt++)                                     \
                _Pragma("unroll")                                              \
                for (int nt = 0; nt < 4; nt++)                                 \
                    mma_tf32(acc[mt][nt], af[mt], bf[nt]);                     \
        }                                                                      \
    }

// ---------------------------------------------------------------------------
// Fused QKV+rel GEMM: A = hs_tf [6144,1024]; B = wcat [3584,1024] (tf32).
// cols [0,3072) -> qkv (ldc 3072, q cols <1024 scaled by 0.125);
// cols [3072,3584) -> rel (ldc 512).
// ---------------------------------------------------------------------------
__global__ __launch_bounds__(256, 2) void gemm_fused(
    const float* __restrict__ A, const float* __restrict__ Bcat,
    const float* __restrict__ bcat, float* __restrict__ qkv,
    float* __restrict__ relv)
{
    extern __shared__ float smem[];
    const uint32_t sb = smem_u32(smem);
    const int tid  = threadIdx.x;
    const int wid  = tid >> 5;
    const int lane = tid & 31;
    const int row0 = blockIdx.y * 128;
    const int col0 = blockIdx.x * 128;
    const int wm   = wid >> 2;
    const int wn   = wid & 3;
    const int lq   = lane >> 2;
    const int lr   = lane & 3;
    const int srow = tid >> 3;
    const int sseg = tid & 7;

    const float* Abase = A    + (size_t)row0 * GK;
    const float* Bbase = Bcat + (size_t)col0 * GK;

    GEMM_MAINLOOP(Abase, Bbase)

    float* C; int ldc; int ccol0;
    if (col0 < 3072) { C = qkv;  ldc = 3072; ccol0 = col0; }
    else             { C = relv; ldc = 512;  ccol0 = col0 - 3072; }

    #pragma unroll
    for (int mt = 0; mt < 4; mt++) {
        int rg0 = row0 + wm*64 + mt*16 + lq;
        #pragma unroll
        for (int nt = 0; nt < 4; nt++) {
            int cl = wn*32 + nt*8 + lr*2;
            float2 bv = *(const float2*)&bcat[col0 + cl];
            float s = (col0 + cl < 1024) ? 0.125f : 1.f;
            float2 o0 = make_float2((acc[mt][nt][0] + bv.x) * s,
                                    (acc[mt][nt][1] + bv.y) * s);
            float2 o1 = make_float2((acc[mt][nt][2] + bv.x) * s,
                                    (acc[mt][nt][3] + bv.y) * s);
            *(float2*)&C[(size_t)rg0 * ldc + ccol0 + cl]       = o0;
            *(float2*)&C[(size_t)(rg0 + 8) * ldc + ccol0 + cl] = o1;
        }
    }
}

// ---------------------------------------------------------------------------
// Plain GEMM (out-proj): C[M,1024] = A @ B^T + bias. Inputs pre-rounded.
// ---------------------------------------------------------------------------
__global__ __launch_bounds__(256, 2) void gemm_plain(
    const float* __restrict__ A, const float* __restrict__ Bm,
    const float* __restrict__ bias, float* __restrict__ C, int N)
{
    extern __shared__ float smem[];
    const uint32_t sb = smem_u32(smem);
    const int tid  = threadIdx.x;
    const int wid  = tid >> 5;
    const int lane = tid & 31;
    const int row0 = blockIdx.y * 128;
    const int col0 = blockIdx.x * 128;
    const int wm   = wid >> 2;
    const int wn   = wid & 3;
    const int lq   = lane >> 2;
    const int lr   = lane & 3;
    const int srow = tid >> 3;
    const int sseg = tid & 7;

    const float* Abase = A  + (size_t)row0 * GK;
    const float* Bbase = Bm + (size_t)col0 * GK;

    GEMM_MAINLOOP(Abase, Bbase)

    #pragma unroll
    for (int mt = 0; mt < 4; mt++) {
        int rg0 = row0 + wm*64 + mt*16 + lq;
        #pragma unroll
        for (int nt = 0; nt < 4; nt++) {
            int cg = col0 + wn*32 + nt*8 + lr*2;
            float2 bv = *(const float2*)&bias[cg];
            float2 o0 = make_float2(acc[mt][nt][0] + bv.x, acc[mt][nt][1] + bv.y);
            float2 o1 = make_float2(acc[mt][nt][2] + bv.x, acc[mt][nt][3] + bv.y);
            *(float2*)&C[(size_t)rg0 * N + cg]       = o0;
            *(float2*)&C[(size_t)(rg0 + 8) * N + cg] = o1;
        }
    }
}

// ---------------------------------------------------------------------------
// Tensor-core attention: split-bf16 3-term mma (unchanged from round 14 win,
// except ctx stores are tf32-rounded so out-proj needs no cvt).
// ---------------------------------------------------------------------------
#define AT_QHI 0
#define AT_QLO 2304
#define AT_KHI 4608
#define AT_KLO 9216
#define AT_VHI 13824
#define AT_VLO 18176
#define AT_SS  22528
#define AT_PHI 30976
#define AT_PLO 35328
#define AT_REL 39680
#define AT_SM  41728
#define AT_SL  41792
#define AT_SSC 41856
#define SMEM_ATTN (41920 * 4)

__global__ __launch_bounds__(256, 1) void attn_mma(
    const float* __restrict__ qkv, const float* __restrict__ rel,
    const float* __restrict__ mask_main, const float* __restrict__ mask_ng,
    const int* __restrict__ ib_main, const int* __restrict__ ib_ng,
    float* __restrict__ ctx)
{
    extern __shared__ float sm_[];
    uint32_t* uQh = (uint32_t*)(sm_ + AT_QHI);
    uint32_t* uQl = (uint32_t*)(sm_ + AT_QLO);
    uint32_t* uKh = (uint32_t*)(sm_ + AT_KHI);
    uint32_t* uKl = (uint32_t*)(sm_ + AT_KLO);
    uint32_t* uVh = (uint32_t*)(sm_ + AT_VHI);
    uint32_t* uVl = (uint32_t*)(sm_ + AT_VLO);
    float*    sS  = sm_ + AT_SS;
    uint32_t* uPh = (uint32_t*)(sm_ + AT_PHI);
    uint32_t* uPl = (uint32_t*)(sm_ + AT_PLO);
    float*    sRel= sm_ + AT_REL;
    float*    sM  = sm_ + AT_SM;
    float*    sL  = sm_ + AT_SL;
    float*    sSc = sm_ + AT_SSC;

    const int bh = blockIdx.y;
    const int b  = bh >> 4;
    const int h  = bh & 15;
    const int z  = blockIdx.z;
    const int is_ng = (z > 0);
    const int n  = z - 1;
    const int t0 = blockIdx.x * 64;
    const int S  = is_ng ? 1024 : 512;
    const int qtok0 = is_ng ? (T_ + n*T_ + t0) : t0;
    const float* maskrow = is_ng ? (mask_ng + (size_t)n * T_ * 1024) : mask_main;
    const int*   brow    = is_ng ? (ib_ng + (size_t)b * T_ * 1024)
                                 : (ib_main + (size_t)b * T_ * 512);

    const int tid  = threadIdx.x;
    const int wid  = tid >> 5;
    const int lane = tid & 31;
    const int lq   = lane >> 2;
    const int lr   = lane & 3;

    #pragma unroll
    for (int p = 0; p < 4; p++) {
        int idx = tid + p*256;
        int r  = idx >> 4;
        int c4 = (idx & 15) << 2;
        float4 v = *(const float4*)(qkv + (size_t)((qtok0 + r)*B_ + b)*3072 + h*D_ + c4);
        uint32_t h0, l0, h1, l1;
        bfsplit2(v.x, v.y, h0, l0);
        bfsplit2(v.z, v.w, h1, l1);
        uQh[r*36 + (c4>>1)]     = h0;  uQh[r*36 + (c4>>1) + 1] = h1;
        uQl[r*36 + (c4>>1)]     = l0;  uQl[r*36 + (c4>>1) + 1] = l1;
    }
    #pragma unroll
    for (int p = 0; p < 8; p++) {
        int idx = tid + p*256;
        int r = idx >> 5, bk = idx & 31;
        sRel[r*32 + bk] = rel[(size_t)((qtok0 + r)*B_ + b)*512 + bk*H_ + h];
    }
    if (tid < 64) { sM[tid] = -1e30f; sL[tid] = 0.f; }

    float accO[2][4][4];
    #pragma unroll
    for (int mt = 0; mt < 2; mt++)
        #pragma unroll
        for (int nt = 0; nt < 4; nt++)
            #pragma unroll
            for (int q = 0; q < 4; q++) accO[mt][nt][q] = 0.f;

    const int wm2 = wid >> 2;
    const int wn2 = wid & 3;
    const int grp = wid >> 2;
    const int wmo = (wid >> 1) & 1;
    const int wno = wid & 1;

    for (int s0 = 0; s0 < S; s0 += 128) {
        bool keep;
        if (!is_ng || s0 < 512) keep = (s0 <= t0 + 63);
        else { int d = s0 - 512; keep = (d > t0 - 128) && (d < t0 + 64); }
        if (!keep) continue;

        __syncthreads();

        #pragma unroll
        for (int p = 0; p < 8; p++) {
            int idx = tid + p*256;
            int sr = idx >> 4;
            int c4 = (idx & 15) << 2;
            int sg = s0 + sr;
            int tok = (!is_ng || sg < T_) ? sg : (T_ + n*T_ + (sg - T_));
            float4 v = *(const float4*)(qkv + (size_t)(tok*B_ + b)*3072 + 1024 + h*D_ + c4);
            uint32_t h0, l0, h1, l1;
            bfsplit2(v.x, v.y, h0, l0);
            bfsplit2(v.z, v.w, h1, l1);
            uKh[sr*36 + (c4>>1)]     = h0;  uKh[sr*36 + (c4>>1) + 1] = h1;
            uKl[sr*36 + (c4>>1)]     = l0;  uKl[sr*36 + (c4>>1) + 1] = l1;
        }
        #pragma unroll
        for (int p = 0; p < 4; p++) {
            int idx = tid + p*256;
            int j  = idx & 63;
            int d4 = (idx >> 6) << 2;
            int sg0 = s0 + 2*j, sg1 = sg0 + 1;
            int tok0 = (!is_ng || sg0 < T_) ? sg0 : (T_ + n*T_ + (sg0 - T_));
            int tok1 = (!is_ng || sg1 < T_) ? sg1 : (T_ + n*T_ + (sg1 - T_));
            float4 v0 = *(const float4*)(qkv + (size_t)(tok0*B_ + b)*3072 + 2048 + h*D_ + d4);
            float4 v1 = *(const float4*)(qkv + (size_t)(tok1*B_ + b)*3072 + 2048 + h*D_ + d4);
            const float e0[4] = {v0.x, v0.y, v0.z, v0.w};
            const float e1[4] = {v1.x, v1.y, v1.z, v1.w};
            #pragma unroll
            for (int i = 0; i < 4; i++) {
                uint32_t hh, ll;
                bfsplit2(e0[i], e1[i], hh, ll);
                uVh[(d4 + i)*68 + j] = hh;
                uVl[(d4 + i)*68 + j] = ll;
            }
        }
        __syncthreads();

        float acc[2][4][4];
        #pragma unroll
        for (int mt = 0; mt < 2; mt++)
            #pragma unroll
            for (int nt = 0; nt < 4; nt++)
                #pragma unroll
                for (int q = 0; q < 4; q++) acc[mt][nt][q] = 0.f;

        #pragma unroll
        for (int ks = 0; ks < 4; ks++) {
            uint32_t ah[2][4], al[2][4], bhv[4][2], blv[4][2];
            #pragma unroll
            for (int mt = 0; mt < 2; mt++) {
                int m = wm2*32 + mt*16 + lq;
                const uint32_t* p = uQh + m*36 + ks*8 + lr;
                ah[mt][0] = p[0]; ah[mt][1] = p[8*36]; ah[mt][2] = p[4]; ah[mt][3] = p[8*36+4];
                const uint32_t* q2 = uQl + m*36 + ks*8 + lr;
                al[mt][0] = q2[0]; al[mt][1] = q2[8*36]; al[mt][2] = q2[4]; al[mt][3] = q2[8*36+4];
            }
            #pragma unroll
            for (int nt = 0; nt < 4; nt++) {
                int nn = wn2*32 + nt*8 + lq;
                const uint32_t* p = uKh + nn*36 + ks*8 + lr;
                bhv[nt][0] = p[0]; bhv[nt][1] = p[4];
                const uint32_t* q2 = uKl + nn*36 + ks*8 + lr;
                blv[nt][0] = q2[0]; blv[nt][1] = q2[4];
            }
            #pragma unroll
            for (int mt = 0; mt < 2; mt++)
                #pragma unroll
                for (int nt = 0; nt < 4; nt++) {
                    mma_bf16(acc[mt][nt], ah[mt], bhv[nt]);
                    mma_bf16(acc[mt][nt], ah[mt], blv[nt]);
                    mma_bf16(acc[mt][nt], al[mt], bhv[nt]);
                }
        }

        #pragma unroll
        for (int mt = 0; mt < 2; mt++) {
            int r0 = wm2*32 + mt*16 + lq, r1 = r0 + 8;
            int tg0 = t0 + r0, tg1 = t0 + r1;
            #pragma unroll
            for (int nt = 0; nt < 4; nt++) {
                int col = wn2*32 + nt*8 + 2*lr;
                int sg  = s0 + col;
                int2   bk0 = *(const int2*)&brow[(size_t)tg0 * S + sg];
                float2 mk0 = *(const float2*)&maskrow[(size_t)tg0 * S + sg];
                float2 o0 = make_float2(acc[mt][nt][0] + sRel[r0*32 + bk0.x] + mk0.x,
                                        acc[mt][nt][1] + sRel[r0*32 + bk0.y] + mk0.y);
                *(float2*)&sS[r0*132 + col] = o0;
                int2   bk1 = *(const int2*)&brow[(size_t)tg1 * S + sg];
                float2 mk1 = *(const float2*)&maskrow[(size_t)tg1 * S + sg];
                float2 o1 = make_float2(acc[mt][nt][2] + sRel[r1*32 + bk1.x] + mk1.x,
                                        acc[mt][nt][3] + sRel[r1*32 + bk1.y] + mk1.y);
                *(float2*)&sS[r1*132 + col] = o1;
            }
        }
        __syncthreads();

        {
            int r = tid >> 2, g = tid & 3;
            float* row = sS + r*132 + g*32;
            float x[32];
            #pragma unroll
            for (int i = 0; i < 8; i++) {
                float4 v = *(const float4*)(row + i*4);
                x[i*4+0] = v.x; x[i*4+1] = v.y; x[i*4+2] = v.z; x[i*4+3] = v.w;
            }
            float mx = -1e30f;
            #pragma unroll
            for (int i = 0; i < 32; i++) mx = fmaxf(mx, x[i]);
            mx = fmaxf(mx, __shfl_xor_sync(0xffffffffu, mx, 1));
            mx = fmaxf(mx, __shfl_xor_sync(0xffffffffu, mx, 2));
            float oldm = sM[r];
            float newm = fmaxf(oldm, mx);
            float sum = 0.f;
            #pragma unroll
            for (int i = 0; i < 32; i++) { x[i] = __expf(x[i] - newm); sum += x[i]; }
            sum += __shfl_xor_sync(0xffffffffu, sum, 1);
            sum += __shfl_xor_sync(0xffffffffu, sum, 2);
            #pragma unroll
            for (int i = 0; i < 16; i++) {
                uint32_t hh, ll;
                bfsplit2(x[2*i], x[2*i+1], hh, ll);
                uPh[r*68 + g*16 + i] = hh;
                uPl[r*68 + g*16 + i] = ll;
            }
            if (g == 0) {
                float scl = __expf(oldm - newm);
                sSc[r] = scl;
                sL[r] = sL[r]*scl + sum;
                sM[r] = newm;
            }
        }
        __syncthreads();

        #pragma unroll
        for (int mt = 0; mt < 2; mt++) {
            float s0r = sSc[wmo*32 + mt*16 + lq];
            float s1r = sSc[wmo*32 + mt*16 + lq + 8];
            #pragma unroll
            for (int nt = 0; nt < 4; nt++) {
                accO[mt][nt][0] *= s0r; accO[mt][nt][1] *= s0r;
                accO[mt][nt][2] *= s1r; accO[mt][nt][3] *= s1r;
            }
        }
        #pragma unroll
        for (int ks = 0; ks < 4; ks++) {
            int kp = grp*32 + ks*8 + lr;
            uint32_t ah[2][4], al[2][4], bhv[4][2], blv[4][2];
            #pragma unroll
            for (int mt = 0; mt < 2; mt++) {
                int m = wmo*32 + mt*16 + lq;
                const uint32_t* p = uPh + m*68 + kp;
                ah[mt][0] = p[0]; ah[mt][1] = p[8*68]; ah[mt][2] = p[4]; ah[mt][3] = p[8*68+4];
                const uint32_t* q2 = uPl + m*68 + kp;
                al[mt][0] = q2[0]; al[mt][1] = q2[8*68]; al[mt][2] = q2[4]; al[mt][3] = q2[8*68+4];
            }
            #pragma unroll
            for (int nt = 0; nt < 4; nt++) {
                int nn = wno*32 + nt*8 + lq;
                const uint32_t* p = uVh + nn*68 + kp;
                bhv[nt][0] = p[0]; bhv[nt][1] = p[4];
                const uint32_t* q2 = uVl + nn*68 + kp;
                blv[nt][0] = q2[0]; blv[nt][1] = q2[4];
            }
            #pragma unroll
            for (int mt = 0; mt < 2; mt++)
                #pragma unroll
                for (int nt = 0; nt < 4; nt++) {
                    mma_bf16(accO[mt][nt], ah[mt], bhv[nt]);
                    mma_bf16(accO[mt][nt], ah[mt], blv[nt]);
                    mma_bf16(accO[mt][nt], al[mt], bhv[nt]);
                }
        }
    }

    // epilogue: reduce s-half groups, normalize, tf32-round, write
    __syncthreads();
    float* sRed = sS;
    if (wid >= 4) {
        #pragma unroll
        for (int mt = 0; mt < 2; mt++) {
            int r0 = wmo*32 + mt*16 + lq, r1 = r0 + 8;
            #pragma unroll
            for (int nt = 0; nt < 4; nt++) {
                int col = wno*32 + nt*8 + 2*lr;
                *(float2*)&sRed[r0*68 + col] = make_float2(accO[mt][nt][0], accO[mt][nt][1]);
                *(float2*)&sRed[r1*68 + col] = make_float2(accO[mt][nt][2], accO[mt][nt][3]);
            }
        }
    }
    __syncthreads();
    if (wid < 4) {
        #pragma unroll
        for (int mt = 0; mt < 2; mt++) {
            int r0 = wmo*32 + mt*16 + lq, r1 = r0 + 8;
            float inv0 = 1.f / sL[r0];
            float inv1 = 1.f / sL[r1];
            #pragma unroll
            for (int nt = 0; nt < 4; nt++) {
                int col = wno*32 + nt*8 + 2*lr;
                float2 q0 = *(const float2*)&sRed[r0*68 + col];
                float2 q1 = *(const float2*)&sRed[r1*68 + col];
                float2 o0 = make_float2(
                    __uint_as_float(f2tfu((accO[mt][nt][0] + q0.x) * inv0)),
                    __uint_as_float(f2tfu((accO[mt][nt][1] + q0.y) * inv0)));
                float2 o1 = make_float2(
                    __uint_as_float(f2tfu((accO[mt][nt][2] + q1.x) * inv1)),
                    __uint_as_float(f2tfu((accO[mt][nt][3] + q1.y) * inv1)));
                *(float2*)(ctx + (size_t)((qtok0 + r0)*B_ + b)*1024 + h*D_ + col) = o0;
                *(float2*)(ctx + (size_t)((qtok0 + r1)*B_ + b)*1024 + h*D_ + col) = o1;
            }
        }
    }
}

// ---------------------------------------------------------------------------
extern "C" void kernel_launch(void* const* d_in, const int* in_sizes, int n_in,
                              void* d_out, int out_size)
{
    const float* hs        = (const float*)d_in[0];   // (1536,4,1024)
    const float* w_in      = (const float*)d_in[1];   // (3072,1024)
    const float* b_in      = (const float*)d_in[2];   // (3072,)
    const float* rw        = (const float*)d_in[3];   // (512,1024)
    const float* rb        = (const float*)d_in[4];   // (512,)
    const float* ow        = (const float*)d_in[5];   // (1024,1024)
    const float* ob        = (const float*)d_in[6];   // (1024,)
    const float* mask_main = (const float*)d_in[7];   // (512,512)
    const float* mask_ng   = (const float*)d_in[8];   // (2,512,1024)
    const int*   ib_main   = (const int*)d_in[9];     // (4,512,512)
    const int*   ib_ng     = (const int*)d_in[10];    // (4,512,1024)
    float* out = (float*)d_out;

    float *qkv, *relv, *ctx, *hs_tf, *wcat, *owt, *bcat;
    cudaGetSymbolAddress((void**)&qkv,   g_qkv);
    cudaGetSymbolAddress((void**)&relv,  g_rel);
    cudaGetSymbolAddress((void**)&ctx,   g_ctx);
    cudaGetSymbolAddress((void**)&hs_tf, g_hs_tf);
    cudaGetSymbolAddress((void**)&wcat,  g_wcat);
    cudaGetSymbolAddress((void**)&owt,   g_owt);
    cudaGetSymbolAddress((void**)&bcat,  g_bcat);

    cudaFuncSetAttribute(gemm_fused, cudaFuncAttributeMaxDynamicSharedMemorySize, SMEM_GEMM);
    cudaFuncSetAttribute(gemm_plain, cudaFuncAttributeMaxDynamicSharedMemorySize, SMEM_GEMM);
    cudaFuncSetAttribute(attn_mma,  cudaFuncAttributeMaxDynamicSharedMemorySize, SMEM_ATTN);

    // pre-round inputs/weights to tf32 (hoists all cvt out of GEMM inner loops)
    cvt_tf32<<<(ROWS_*1024/4 + 255)/256, 256>>>(hs,   hs_tf, ROWS_*1024/4);
    cvt_tf32<<<(3072*1024/4 + 255)/256, 256>>>(w_in, wcat,              3072*1024/4);
    cvt_tf32<<<(512*1024/4  + 255)/256, 256>>>(rw,   wcat + 3072*1024,  512*1024/4);
    cvt_tf32<<<(1024*1024/4 + 255)/256, 256>>>(ow,   owt,               1024*1024/4);
    cudaMemcpyAsync(bcat,        b_in, 3072*sizeof(float), cudaMemcpyDeviceToDevice);
    cudaMemcpyAsync(bcat + 3072, rb,    512*sizeof(float), cudaMemcpyDeviceToDevice);

    // fused QKV + rel projection (q cols pre-scaled by 0.125 in epilogue)
    gemm_fused<<<dim3(NCAT/128, ROWS_/128), 256, SMEM_GEMM>>>(
        hs_tf, wcat, bcat, qkv, relv);
    // fused attention (tensor cores): z=0 main, z=1,2 ngram
    attn_mma<<<dim3(T_/64, B_*H_, 3), 256, SMEM_ATTN>>>(
        qkv, relv, mask_main, mask_ng, ib_main, ib_ng, ctx);
    // out projection directly into d_out (ctx already tf32-rounded)
    gemm_plain<<<dim3(1024/128, ROWS_/128), 256, SMEM_GEMM>>>(
        ctx, owt, ob, out, 1024);
}

// round 16
// speedup vs baseline: 3.6674x; 1.1164x over previous
#include <cuda_runtime.h>
#include <cuda_bf16.h>
#include <cstdint>

#define T_ 512
#define B_ 4
#define H_ 16
#define D_ 64
#define NBKT 32
#define TOKENS 1536           // (1+NGRAM)*T
#define ROWS_ (TOKENS * B_)   // 6144
#define GK 1024               // K for all GEMMs
#define BK 32                 // K chunk
#define NCHUNK (GK / BK)      // 32
#define TILE_F (128 * 32)     // 4096 floats per tile (128 rows x 32 k, swizzled)
#define STAGE_F (2 * TILE_F)  // A tile + B tile per stage
#define NSTAGE 3
#define SMEM_GEMM (NSTAGE * STAGE_F * 4)   // 98304 B
#define NCAT 3584             // fused qkv(3072) + rel(512) output cols

typedef unsigned long long ull;

// Scratch (device globals: allocation-free rule)
__device__ float g_qkv[ROWS_ * 3072];   // q|k|v per row, q pre-scaled by 1/8
__device__ float g_rel[ROWS_ * 512];    // rel-value table, col = bucket*16 + head
__device__ float g_ctx[ROWS_ * 1024];   // attention out (tf32, k-permuted)
__device__ float g_hs_tf[ROWS_ * 1024]; // hs tf32, k-permuted
__device__ float g_wcat[NCAT * 1024];   // [w_in; rel_w] tf32, k-permuted
__device__ float g_owt[1024 * 1024];    // out_w tf32, k-permuted
__device__ float g_bcat[NCAT];          // [b_in; rel_b]

// ---- tf32 helpers (arch-generic: sm_80+) ----
__device__ __forceinline__ uint32_t f2tfu(float f) {
    uint32_t r; asm("cvt.rna.tf32.f32 %0, %1;" : "=r"(r) : "f"(f));
    return r;
}
__device__ __forceinline__ void mma_tf32(float* c, const uint32_t* a, const uint32_t* b) {
    asm volatile(
        "mma.sync.aligned.m16n8k8.row.col.f32.tf32.tf32.f32 "
        "{%0,%1,%2,%3}, {%4,%5,%6,%7}, {%8,%9}, {%0,%1,%2,%3};"
        : "+f"(c[0]), "+f"(c[1]), "+f"(c[2]), "+f"(c[3])
        : "r"(a[0]), "r"(a[1]), "r"(a[2]), "r"(a[3]), "r"(b[0]), "r"(b[1]));
}
// ---- bf16 helpers ----
__device__ __forceinline__ void mma_bf16(float* c, const uint32_t* a, const uint32_t* b) {
    asm volatile(
        "mma.sync.aligned.m16n8k16.row.col.f32.bf16.bf16.f32 "
        "{%0,%1,%2,%3}, {%4,%5,%6,%7}, {%8,%9}, {%0,%1,%2,%3};"
        : "+f"(c[0]), "+f"(c[1]), "+f"(c[2]), "+f"(c[3])
        : "r"(a[0]), "r"(a[1]), "r"(a[2]), "r"(a[3]), "r"(b[0]), "r"(b[1]));
}
__device__ __forceinline__ uint32_t bf2(float e0, float e1) {
    uint32_t r; asm("cvt.rn.bf16x2.f32 %0, %1, %2;" : "=r"(r) : "f"(e1), "f"(e0));
    return r;
}
__device__ __forceinline__ void bfsplit2(float x, float y, uint32_t& uh, uint32_t& ul) {
    uh = bf2(x, y);
    float hx = __uint_as_float((uh & 0xffffu) << 16);
    float hy = __uint_as_float(uh & 0xffff0000u);
    ul = bf2(x - hx, y - hy);
}
__device__ __forceinline__ uint32_t smem_u32(const void* p) {
    uint32_t a;
    asm("{ .reg .u64 t; cvta.to.shared.u64 t, %1; cvt.u32.u64 %0, t; }" : "=r"(a) : "l"(p));
    return a;
}
__device__ __forceinline__ void cp16(uint32_t dst, const void* src) {
    asm volatile("cp.async.ca.shared.global [%0], [%1], 16;" :: "r"(dst), "l"(src));
}

// ---------------------------------------------------------------------------
// tf32 round + k-group permutation: each 8-float group [o0..o7] is stored as
// [o0,o4,o1,o5,o2,o6,o3,o7] so that mma fragment pairs (k=lr, k=lr+4) are
// contiguous 8 bytes -> LDS.64 fragment loads in the GEMM.
// ---------------------------------------------------------------------------
__global__ __launch_bounds__(256) void cvt_perm(
    const float* __restrict__ src, float* __restrict__ dst, int n8)
{
    int i = blockIdx.x * 256 + threadIdx.x;
    if (i < n8) {
        const float4* s = (const float4*)(src + (size_t)i * 8);
        float4 v0 = s[0], v1 = s[1];
        float4 w0, w1;
        w0.x = __uint_as_float(f2tfu(v0.x));
        w0.y = __uint_as_float(f2tfu(v1.x));
        w0.z = __uint_as_float(f2tfu(v0.y));
        w0.w = __uint_as_float(f2tfu(v1.y));
        w1.x = __uint_as_float(f2tfu(v0.z));
        w1.y = __uint_as_float(f2tfu(v1.z));
        w1.z = __uint_as_float(f2tfu(v0.w));
        w1.w = __uint_as_float(f2tfu(v1.w));
        float4* d = (float4*)(dst + (size_t)i * 8);
        d[0] = w0; d[1] = w1;
    }
}

// ---------------------------------------------------------------------------
// GEMM mainloop (k-permuted tf32 inputs, XOR-swizzled smem, LDS.64 fragments)
// smem tile: 128 rows x 32 floats; unit (8B) u at row r stored at u^((r&3)<<2).
// ---------------------------------------------------------------------------
#define GEMM_MAINLOOP(Abase, Bbase)                                            \
    float acc[4][4][4];                                                        \
    _Pragma("unroll")                                                          \
    for (int i = 0; i < 4; i++)                                                \
        _Pragma("unroll")                                                      \
        for (int j = 0; j < 4; j++)                                            \
            _Pragma("unroll")                                                  \
            for (int q = 0; q < 4; q++) acc[i][j][q] = 0.f;                    \
    auto issue_chunk = [&](int chunk, int stg) {                               \
        const int k0 = chunk * BK;                                             \
        const uint32_t as = sb + (uint32_t)(stg * STAGE_F) * 4u;               \
        const uint32_t bs = as + (uint32_t)TILE_F * 4u;                        \
        _Pragma("unroll")                                                      \
        for (int j = 0; j < 4; j++) {                                          \
            int row = srow + j * 32;                                           \
            uint32_t off = (uint32_t)(row * 32 +                               \
                (((2 * sseg) ^ ((row & 3) << 2)) << 1)) * 4u;                  \
            cp16(as + off, Abase + (size_t)row * GK + k0 + sseg * 4);          \
        }                                                                      \
        _Pragma("unroll")                                                      \
        for (int j = 0; j < 4; j++) {                                          \
            int row = srow + j * 32;                                           \
            uint32_t off = (uint32_t)(row * 32 +                               \
                (((2 * sseg) ^ ((row & 3) << 2)) << 1)) * 4u;                  \
            cp16(bs + off, Bbase + (size_t)row * GK + k0 + sseg * 4);          \
        }                                                                      \
        asm volatile("cp.async.commit_group;" ::: "memory");                   \
    };                                                                         \
    issue_chunk(0, 0);                                                         \
    issue_chunk(1, 1);                                                         \
    const uint32_t sa = (lq & 3) << 2;                                         \
    for (int it = 0; it < NCHUNK; it++) {                                      \
        const int stg = it % NSTAGE;                                           \
        if (it + 1 < NCHUNK) {                                                 \
            asm volatile("cp.async.wait_group 1;" ::: "memory");               \
        } else {                                                               \
            asm volatile("cp.async.wait_group 0;" ::: "memory");               \
        }                                                                      \
        __syncthreads();                                                       \
        if (it + 2 < NCHUNK) issue_chunk(it + 2, (it + 2) % NSTAGE);           \
        const uint32_t* As = (const uint32_t*)(smem + stg * STAGE_F);          \
        const uint32_t* Bs = As + TILE_F;                                      \
        const uint32_t* Aw = As + (wm * 64 + lq) * 32;                         \
        const uint32_t* Bw = Bs + (wn * 32 + lq) * 32;                         \
        _Pragma("unroll")                                                      \
        for (int ks = 0; ks < 4; ks++) {                                       \
            const uint32_t uoff = (((uint32_t)(ks * 4 + lr)) ^ sa) << 1;       \
            uint32_t af[4][4], bf[4][2];                                       \
            _Pragma("unroll")                                                  \
            for (int mt = 0; mt < 4; mt++) {                                   \
                const uint32_t* pr = Aw + mt * 16 * 32;                        \
                uint2 lo = *(const uint2*)(pr + uoff);                         \
                uint2 hi = *(const uint2*)(pr + 8 * 32 + uoff);                \
                af[mt][0] = lo.x; af[mt][1] = hi.x;                            \
                af[mt][2] = lo.y; af[mt][3] = hi.y;                            \
            }                                                                  \
            _Pragma("unroll")                                                  \
            for (int nt = 0; nt < 4; nt++) {                                   \
                const uint32_t* pb = Bw + nt * 8 * 32;                         \
                uint2 bb = *(const uint2*)(pb + uoff);                         \
                bf[nt][0] = bb.x; bf[nt][1] = bb.y;                            \
            }                                                                  \
            _Pragma("unroll")                                                  \
            for (int mt = 0; mt < 4; mt++)                                     \
                _Pragma("unroll")                                              \
                for (int nt = 0; nt < 4; nt++)                                 \
                    mma_tf32(acc[mt][nt], af[mt], bf[nt]);                     \
        }                                                                      \
    }

// ---------------------------------------------------------------------------
// Fused QKV+rel GEMM: A = hs_tf [6144,1024]p; B = wcat [3584,1024]p.
// cols [0,3072) -> qkv (ldc 3072, q cols <1024 scaled by 0.125);
// cols [3072,3584) -> rel (ldc 512).
// ---------------------------------------------------------------------------
__global__ __launch_bounds__(256, 2) void gemm_fused(
    const float* __restrict__ A, const float* __restrict__ Bcat,
    const float* __restrict__ bcat, float* __restrict__ qkv,
    float* __restrict__ relv)
{
    extern __shared__ float smem[];
    const uint32_t sb = smem_u32(smem);
    const int tid  = threadIdx.x;
    const int wid  = tid >> 5;
    const int lane = tid & 31;
    const int row0 = blockIdx.y * 128;
    const int col0 = blockIdx.x * 128;
    const int wm   = wid >> 2;
    const int wn   = wid & 3;
    const int lq   = lane >> 2;
    const int lr   = lane & 3;
    const int srow = tid >> 3;
    const int sseg = tid & 7;

    const float* Abase = A    + (size_t)row0 * GK;
    const float* Bbase = Bcat + (size_t)col0 * GK;

    GEMM_MAINLOOP(Abase, Bbase)

    float* C; int ldc; int ccol0;
    if (col0 < 3072) { C = qkv;  ldc = 3072; ccol0 = col0; }
    else             { C = relv; ldc = 512;  ccol0 = col0 - 3072; }

    #pragma unroll
    for (int mt = 0; mt < 4; mt++) {
        int rg0 = row0 + wm*64 + mt*16 + lq;
        #pragma unroll
        for (int nt = 0; nt < 4; nt++) {
            int cl = wn*32 + nt*8 + lr*2;
            float2 bv = *(const float2*)&bcat[col0 + cl];
            float s = (col0 + cl < 1024) ? 0.125f : 1.f;
            float2 o0 = make_float2((acc[mt][nt][0] + bv.x) * s,
                                    (acc[mt][nt][1] + bv.y) * s);
            float2 o1 = make_float2((acc[mt][nt][2] + bv.x) * s,
                                    (acc[mt][nt][3] + bv.y) * s);
            *(float2*)&C[(size_t)rg0 * ldc + ccol0 + cl]       = o0;
            *(float2*)&C[(size_t)(rg0 + 8) * ldc + ccol0 + cl] = o1;
        }
    }
}

// ---------------------------------------------------------------------------
// Plain GEMM (out-proj): C[M,1024] = A @ B^T + bias. k-permuted tf32 inputs.
// ---------------------------------------------------------------------------
__global__ __launch_bounds__(256, 2) void gemm_plain(
    const float* __restrict__ A, const float* __restrict__ Bm,
    const float* __restrict__ bias, float* __restrict__ C, int N)
{
    extern __shared__ float smem[];
    const uint32_t sb = smem_u32(smem);
    const int tid  = threadIdx.x;
    const int wid  = tid >> 5;
    const int lane = tid & 31;
    const int row0 = blockIdx.y * 128;
    const int col0 = blockIdx.x * 128;
    const int wm   = wid >> 2;
    const int wn   = wid & 3;
    const int lq   = lane >> 2;
    const int lr   = lane & 3;
    const int srow = tid >> 3;
    const int sseg = tid & 7;

    const float* Abase = A  + (size_t)row0 * GK;
    const float* Bbase = Bm + (size_t)col0 * GK;

    GEMM_MAINLOOP(Abase, Bbase)

    #pragma unroll
    for (int mt = 0; mt < 4; mt++) {
        int rg0 = row0 + wm*64 + mt*16 + lq;
        #pragma unroll
        for (int nt = 0; nt < 4; nt++) {
            int cg = col0 + wn*32 + nt*8 + lr*2;
            float2 bv = *(const float2*)&bias[cg];
            float2 o0 = make_float2(acc[mt][nt][0] + bv.x, acc[mt][nt][1] + bv.y);
            float2 o1 = make_float2(acc[mt][nt][2] + bv.x, acc[mt][nt][3] + bv.y);
            *(float2*)&C[(size_t)rg0 * N + cg]       = o0;
            *(float2*)&C[(size_t)(rg0 + 8) * N + cg] = o1;
        }
    }
}

// ---------------------------------------------------------------------------
// Tensor-core attention (round-14 design). Epilogue writes ctx tf32-rounded
// in the k-PERMUTED layout so gemm_plain consumes it directly.
// ---------------------------------------------------------------------------
#define AT_QHI 0
#define AT_QLO 2304
#define AT_KHI 4608
#define AT_KLO 9216
#define AT_VHI 13824
#define AT_VLO 18176
#define AT_SS  22528
#define AT_PHI 30976
#define AT_PLO 35328
#define AT_REL 39680
#define AT_SM  41728
#define AT_SL  41792
#define AT_SSC 41856
#define SMEM_ATTN (41920 * 4)

// orig offset o within an 8-float k-group -> stored (permuted) offset
__device__ __forceinline__ int perm8(int o) { return (o < 4) ? 2*o : 2*o - 7; }

__global__ __launch_bounds__(256, 1) void attn_mma(
    const float* __restrict__ qkv, const float* __restrict__ rel,
    const float* __restrict__ mask_main, const float* __restrict__ mask_ng,
    const int* __restrict__ ib_main, const int* __restrict__ ib_ng,
    float* __restrict__ ctx)
{
    extern __shared__ float sm_[];
    uint32_t* uQh = (uint32_t*)(sm_ + AT_QHI);
    uint32_t* uQl = (uint32_t*)(sm_ + AT_QLO);
    uint32_t* uKh = (uint32_t*)(sm_ + AT_KHI);
    uint32_t* uKl = (uint32_t*)(sm_ + AT_KLO);
    uint32_t* uVh = (uint32_t*)(sm_ + AT_VHI);
    uint32_t* uVl = (uint32_t*)(sm_ + AT_VLO);
    float*    sS  = sm_ + AT_SS;
    uint32_t* uPh = (uint32_t*)(sm_ + AT_PHI);
    uint32_t* uPl = (uint32_t*)(sm_ + AT_PLO);
    float*    sRel= sm_ + AT_REL;
    float*    sM  = sm_ + AT_SM;
    float*    sL  = sm_ + AT_SL;
    float*    sSc = sm_ + AT_SSC;

    const int bh = blockIdx.y;
    const int b  = bh >> 4;
    const int h  = bh & 15;
    const int z  = blockIdx.z;
    const int is_ng = (z > 0);
    const int n  = z - 1;
    const int t0 = blockIdx.x * 64;
    const int S  = is_ng ? 1024 : 512;
    const int qtok0 = is_ng ? (T_ + n*T_ + t0) : t0;
    const float* maskrow = is_ng ? (mask_ng + (size_t)n * T_ * 1024) : mask_main;
    const int*   brow    = is_ng ? (ib_ng + (size_t)b * T_ * 1024)
                                 : (ib_main + (size_t)b * T_ * 512);

    const int tid  = threadIdx.x;
    const int wid  = tid >> 5;
    const int lane = tid & 31;
    const int lq   = lane >> 2;
    const int lr   = lane & 3;

    #pragma unroll
    for (int p = 0; p < 4; p++) {
        int idx = tid + p*256;
        int r  = idx >> 4;
        int c4 = (idx & 15) << 2;
        float4 v = *(const float4*)(qkv + (size_t)((qtok0 + r)*B_ + b)*3072 + h*D_ + c4);
        uint32_t h0, l0, h1, l1;
        bfsplit2(v.x, v.y, h0, l0);
        bfsplit2(v.z, v.w, h1, l1);
        uQh[r*36 + (c4>>1)]     = h0;  uQh[r*36 + (c4>>1) + 1] = h1;
        uQl[r*36 + (c4>>1)]     = l0;  uQl[r*36 + (c4>>1) + 1] = l1;
    }
    #pragma unroll
    for (int p = 0; p < 8; p++) {
        int idx = tid + p*256;
        int r = idx >> 5, bk = idx & 31;
        sRel[r*32 + bk] = rel[(size_t)((qtok0 + r)*B_ + b)*512 + bk*H_ + h];
    }
    if (tid < 64) { sM[tid] = -1e30f; sL[tid] = 0.f; }

    float accO[2][4][4];
    #pragma unroll
    for (int mt = 0; mt < 2; mt++)
        #pragma unroll
        for (int nt = 0; nt < 4; nt++)
            #pragma unroll
            for (int q = 0; q < 4; q++) accO[mt][nt][q] = 0.f;

    const int wm2 = wid >> 2;
    const int wn2 = wid & 3;
    const int grp = wid >> 2;
    const int wmo = (wid >> 1) & 1;
    const int wno = wid & 1;

    for (int s0 = 0; s0 < S; s0 += 128) {
        bool keep;
        if (!is_ng || s0 < 512) keep = (s0 <= t0 + 63);
        else { int d = s0 - 512; keep = (d > t0 - 128) && (d < t0 + 64); }
        if (!keep) continue;

        __syncthreads();

        #pragma unroll
        for (int p = 0; p < 8; p++) {
            int idx = tid + p*256;
            int sr = idx >> 4;
            int c4 = (idx & 15) << 2;
            int sg = s0 + sr;
            int tok = (!is_ng || sg < T_) ? sg : (T_ + n*T_ + (sg - T_));
            float4 v = *(const float4*)(qkv + (size_t)(tok*B_ + b)*3072 + 1024 + h*D_ + c4);
            uint32_t h0, l0, h1, l1;
            bfsplit2(v.x, v.y, h0, l0);
            bfsplit2(v.z, v.w, h1, l1);
            uKh[sr*36 + (c4>>1)]     = h0;  uKh[sr*36 + (c4>>1) + 1] = h1;
            uKl[sr*36 + (c4>>1)]     = l0;  uKl[sr*36 + (c4>>1) + 1] = l1;
        }
        #pragma unroll
        for (int p = 0; p < 4; p++) {
            int idx = tid + p*256;
            int j  = idx & 63;
            int d4 = (idx >> 6) << 2;
            int sg0 = s0 + 2*j, sg1 = sg0 + 1;
            int tok0 = (!is_ng || sg0 < T_) ? sg0 : (T_ + n*T_ + (sg0 - T_));
            int tok1 = (!is_ng || sg1 < T_) ? sg1 : (T_ + n*T_ + (sg1 - T_));
            float4 v0 = *(const float4*)(qkv + (size_t)(tok0*B_ + b)*3072 + 2048 + h*D_ + d4);
            float4 v1 = *(const float4*)(qkv + (size_t)(tok1*B_ + b)*3072 + 2048 + h*D_ + d4);
            const float e0[4] = {v0.x, v0.y, v0.z, v0.w};
            const float e1[4] = {v1.x, v1.y, v1.z, v1.w};
            #pragma unroll
            for (int i = 0; i < 4; i++) {
                uint32_t hh, ll;
                bfsplit2(e0[i], e1[i], hh, ll);
                uVh[(d4 + i)*68 + j] = hh;
                uVl[(d4 + i)*68 + j] = ll;
            }
        }
        __syncthreads();

        float acc[2][4][4];
        #pragma unroll
        for (int mt = 0; mt < 2; mt++)
            #pragma unroll
            for (int nt = 0; nt < 4; nt++)
                #pragma unroll
                for (int q = 0; q < 4; q++) acc[mt][nt][q] = 0.f;

        #pragma unroll
        for (int ks = 0; ks < 4; ks++) {
            uint32_t ah[2][4], al[2][4], bhv[4][2], blv[4][2];
            #pragma unroll
            for (int mt = 0; mt < 2; mt++) {
                int m = wm2*32 + mt*16 + lq;
                const uint32_t* p = uQh + m*36 + ks*8 + lr;
                ah[mt][0] = p[0]; ah[mt][1] = p[8*36]; ah[mt][2] = p[4]; ah[mt][3] = p[8*36+4];
                const uint32_t* q2 = uQl + m*36 + ks*8 + lr;
                al[mt][0] = q2[0]; al[mt][1] = q2[8*36]; al[mt][2] = q2[4]; al[mt][3] = q2[8*36+4];
            }
            #pragma unroll
            for (int nt = 0; nt < 4; nt++) {
                int nn = wn2*32 + nt*8 + lq;
                const uint32_t* p = uKh + nn*36 + ks*8 + lr;
                bhv[nt][0] = p[0]; bhv[nt][1] = p[4];
                const uint32_t* q2 = uKl + nn*36 + ks*8 + lr;
                blv[nt][0] = q2[0]; blv[nt][1] = q2[4];
            }
            #pragma unroll
            for (int mt = 0; mt < 2; mt++)
                #pragma unroll
                for (int nt = 0; nt < 4; nt++) {
                    mma_bf16(acc[mt][nt], ah[mt], bhv[nt]);
                    mma_bf16(acc[mt][nt], ah[mt], blv[nt]);
                    mma_bf16(acc[mt][nt], al[mt], bhv[nt]);
                }
        }

        #pragma unroll
        for (int mt = 0; mt < 2; mt++) {
            int r0 = wm2*32 + mt*16 + lq, r1 = r0 + 8;
            int tg0 = t0 + r0, tg1 = t0 + r1;
            #pragma unroll
            for (int nt = 0; nt < 4; nt++) {
                int col = wn2*32 + nt*8 + 2*lr;
                int sg  = s0 + col;
                int2   bk0 = *(const int2*)&brow[(size_t)tg0 * S + sg];
                float2 mk0 = *(const float2*)&maskrow[(size_t)tg0 * S + sg];
                float2 o0 = make_float2(acc[mt][nt][0] + sRel[r0*32 + bk0.x] + mk0.x,
                                        acc[mt][nt][1] + sRel[r0*32 + bk0.y] + mk0.y);
                *(float2*)&sS[r0*132 + col] = o0;
                int2   bk1 = *(const int2*)&brow[(size_t)tg1 * S + sg];
                float2 mk1 = *(const float2*)&maskrow[(size_t)tg1 * S + sg];
                float2 o1 = make_float2(acc[mt][nt][2] + sRel[r1*32 + bk1.x] + mk1.x,
                                        acc[mt][nt][3] + sRel[r1*32 + bk1.y] + mk1.y);
                *(float2*)&sS[r1*132 + col] = o1;
            }
        }
        __syncthreads();

        {
            int r = tid >> 2, g = tid & 3;
            float* row = sS + r*132 + g*32;
            float x[32];
            #pragma unroll
            for (int i = 0; i < 8; i++) {
                float4 v = *(const float4*)(row + i*4);
                x[i*4+0] = v.x; x[i*4+1] = v.y; x[i*4+2] = v.z; x[i*4+3] = v.w;
            }
            float mx = -1e30f;
            #pragma unroll
            for (int i = 0; i < 32; i++) mx = fmaxf(mx, x[i]);
            mx = fmaxf(mx, __shfl_xor_sync(0xffffffffu, mx, 1));
            mx = fmaxf(mx, __shfl_xor_sync(0xffffffffu, mx, 2));
            float oldm = sM[r];
            float newm = fmaxf(oldm, mx);
            float sum = 0.f;
            #pragma unroll
            for (int i = 0; i < 32; i++) { x[i] = __expf(x[i] - newm); sum += x[i]; }
            sum += __shfl_xor_sync(0xffffffffu, sum, 1);
            sum += __shfl_xor_sync(0xffffffffu, sum, 2);
            #pragma unroll
            for (int i = 0; i < 16; i++) {
                uint32_t hh, ll;
                bfsplit2(x[2*i], x[2*i+1], hh, ll);
                uPh[r*68 + g*16 + i] = hh;
                uPl[r*68 + g*16 + i] = ll;
            }
            if (g == 0) {
                float scl = __expf(oldm - newm);
                sSc[r] = scl;
                sL[r] = sL[r]*scl + sum;
                sM[r] = newm;
            }
        }
        __syncthreads();

        #pragma unroll
        for (int mt = 0; mt < 2; mt++) {
            float s0r = sSc[wmo*32 + mt*16 + lq];
            float s1r = sSc[wmo*32 + mt*16 + lq + 8];
            #pragma unroll
            for (int nt = 0; nt < 4; nt++) {
                accO[mt][nt][0] *= s0r; accO[mt][nt][1] *= s0r;
                accO[mt][nt][2] *= s1r; accO[mt][nt][3] *= s1r;
            }
        }
        #pragma unroll
        for (int ks = 0; ks < 4; ks++) {
            int kp = grp*32 + ks*8 + lr;
            uint32_t ah[2][4], al[2][4], bhv[4][2], blv[4][2];
            #pragma unroll
            for (int mt = 0; mt < 2; mt++) {
                int m = wmo*32 + mt*16 + lq;
                const uint32_t* p = uPh + m*68 + kp;
                ah[mt][0] = p[0]; ah[mt][1] = p[8*68]; ah[mt][2] = p[4]; ah[mt][3] = p[8*68+4];
                const uint32_t* q2 = uPl + m*68 + kp;
                al[mt][0] = q2[0]; al[mt][1] = q2[8*68]; al[mt][2] = q2[4]; al[mt][3] = q2[8*68+4];
            }
            #pragma unroll
            for (int nt = 0; nt < 4; nt++) {
                int nn = wno*32 + nt*8 + lq;
                const uint32_t* p = uVh + nn*68 + kp;
                bhv[nt][0] = p[0]; bhv[nt][1] = p[4];
                const uint32_t* q2 = uVl + nn*68 + kp;
                blv[nt][0] = q2[0]; blv[nt][1] = q2[4];
            }
            #pragma unroll
            for (int mt = 0; mt < 2; mt++)
                #pragma unroll
                for (int nt = 0; nt < 4; nt++) {
                    mma_bf16(accO[mt][nt], ah[mt], bhv[nt]);
                    mma_bf16(accO[mt][nt], ah[mt], blv[nt]);
                    mma_bf16(accO[mt][nt], al[mt], bhv[nt]);
                }
        }
    }

    // epilogue: reduce s-half groups, normalize, tf32-round, permuted write
    __syncthreads();
    float* sRed = sS;
    if (wid >= 4) {
        #pragma unroll
        for (int mt = 0; mt < 2; mt++) {
            int r0 = wmo*32 + mt*16 + lq, r1 = r0 + 8;
            #pragma unroll
            for (int nt = 0; nt < 4; nt++) {
                int col = wno*32 + nt*8 + 2*lr;
                *(float2*)&sRed[r0*68 + col] = make_float2(accO[mt][nt][0], accO[mt][nt][1]);
                *(float2*)&sRed[r1*68 + col] = make_float2(accO[mt][nt][2], accO[mt][nt][3]);
            }
        }
    }
    __syncthreads();
    if (wid < 4) {
        // orig cols (2lr, 2lr+1) within 8-group -> permuted offsets
        const int p0 = perm8(2*lr);
        const int p1 = perm8(2*lr + 1);
        #pragma unroll
        for (int mt = 0; mt < 2; mt++) {
            int r0 = wmo*32 + mt*16 + lq, r1 = r0 + 8;
            float inv0 = 1.f / sL[r0];
            float inv1 = 1.f / sL[r1];
            #pragma unroll
            for (int nt = 0; nt < 4; nt++) {
                int col  = wno*32 + nt*8 + 2*lr;
                int colg = wno*32 + nt*8;           // 8-group base
                float2 q0 = *(const float2*)&sRed[r0*68 + col];
                float2 q1 = *(const float2*)&sRed[r1*68 + col];
                float v00 = __uint_as_float(f2tfu((accO[mt][nt][0] + q0.x) * inv0));
                float v01 = __uint_as_float(f2tfu((accO[mt][nt][1] + q0.y) * inv0));
                float v10 = __uint_as_float(f2tfu((accO[mt][nt][2] + q1.x) * inv1));
                float v11 = __uint_as_float(f2tfu((accO[mt][nt][3] + q1.y) * inv1));
                float* c0 = ctx + (size_t)((qtok0 + r0)*B_ + b)*1024 + h*D_ + colg;
                float* c1 = ctx + (size_t)((qtok0 + r1)*B_ + b)*1024 + h*D_ + colg;
                c0[p0] = v00; c0[p1] = v01;
                c1[p0] = v10; c1[p1] = v11;
            }
        }
    }
}

// ---------------------------------------------------------------------------
extern "C" void kernel_launch(void* const* d_in, const int* in_sizes, int n_in,
                              void* d_out, int out_size)
{
    const float* hs        = (const float*)d_in[0];   // (1536,4,1024)
    const float* w_in      = (const float*)d_in[1];   // (3072,1024)
    const float* b_in      = (const float*)d_in[2];   // (3072,)
    const float* rw        = (const float*)d_in[3];   // (512,1024)
    const float* rb        = (const float*)d_in[4];   // (512,)
    const float* ow        = (const float*)d_in[5];   // (1024,1024)
    const float* ob        = (const float*)d_in[6];   // (1024,)
    const float* mask_main = (const float*)d_in[7];   // (512,512)
    const float* mask_ng   = (const float*)d_in[8];   // (2,512,1024)
    const int*   ib_main   = (const int*)d_in[9];     // (4,512,512)
    const int*   ib_ng     = (const int*)d_in[10];    // (4,512,1024)
    float* out = (float*)d_out;

    float *qkv, *relv, *ctx, *hs_tf, *wcat, *owt, *bcat;
    cudaGetSymbolAddress((void**)&qkv,   g_qkv);
    cudaGetSymbolAddress((void**)&relv,  g_rel);
    cudaGetSymbolAddress((void**)&ctx,   g_ctx);
    cudaGetSymbolAddress((void**)&hs_tf, g_hs_tf);
    cudaGetSymbolAddress((void**)&wcat,  g_wcat);
    cudaGetSymbolAddress((void**)&owt,   g_owt);
    cudaGetSymbolAddress((void**)&bcat,  g_bcat);

    cudaFuncSetAttribute(gemm_fused, cudaFuncAttributeMaxDynamicSharedMemorySize, SMEM_GEMM);
    cudaFuncSetAttribute(gemm_plain, cudaFuncAttributeMaxDynamicSharedMemorySize, SMEM_GEMM);
    cudaFuncSetAttribute(attn_mma,  cudaFuncAttributeMaxDynamicSharedMemorySize, SMEM_ATTN);

    // tf32 round + k-group permutation (fragment pairs become contiguous)
    cvt_perm<<<(ROWS_*1024/8 + 255)/256, 256>>>(hs,   hs_tf, ROWS_*1024/8);
    cvt_perm<<<(3072*1024/8 + 255)/256, 256>>>(w_in, wcat,             3072*1024/8);
    cvt_perm<<<(512*1024/8  + 255)/256, 256>>>(rw,   wcat + 3072*1024, 512*1024/8);
    cvt_perm<<<(1024*1024/8 + 255)/256, 256>>>(ow,   owt,              1024*1024/8);
    cudaMemcpyAsync(bcat,        b_in, 3072*sizeof(float), cudaMemcpyDeviceToDevice);
    cudaMemcpyAsync(bcat + 3072, rb,    512*sizeof(float), cudaMemcpyDeviceToDevice);

    // fused QKV + rel projection
    gemm_fused<<<dim3(NCAT/128, ROWS_/128), 256, SMEM_GEMM>>>(
        hs_tf, wcat, bcat, qkv, relv);
    // fused attention (tensor cores)
    attn_mma<<<dim3(T_/64, B_*H_, 3), 256, SMEM_ATTN>>>(
        qkv, relv, mask_main, mask_ng, ib_main, ib_ng, ctx);
    // out projection directly into d_out (ctx already tf32 + permuted)
    gemm_plain<<<dim3(1024/128, ROWS_/128), 256, SMEM_GEMM>>>(
        ctx, owt, ob, out, 1024);
}